// round 4
// baseline (speedup 1.0000x reference)
#include <cuda_runtime.h>
#include <cstdint>

#define TT 4096
#define DD 2048
#define HH 8192
#define NE 8
#define RRK 16
#define ER 128
#define SCAL 2.0f

#define BM 128
#define BN 128
#define BK 32
#define NS 3
#define ASZ 16384                 // A tile bytes per stage (128 x 32 x 4)
#define STAGE 32768               // (A + B) per stage
#define SMEMSZ (NS * STAGE)       // 96 KB -> 2 CTAs/SM

// ---------------- scratch (device globals) ------------------------------------
__device__ float g_Y  [(size_t)TT * HH];
__device__ float g_Z1 [TT * ER];
__device__ float g_Z2 [TT * ER];

// ---------------- helpers ------------------------------------------------------
__device__ __forceinline__ void cp16(uint32_t s, const void* g) {
    asm volatile("cp.async.ca.shared.global [%0], [%1], 16;" :: "r"(s), "l"(g));
}
__device__ __forceinline__ uint32_t smem_u32(const void* p) {
    uint32_t a;
    asm("{ .reg .u64 t; cvta.to.shared.u64 t, %1; cvt.u32.u64 %0, t; }" : "=r"(a) : "l"(p));
    return a;
}
__device__ __forceinline__ uint32_t tf32b(uint32_t x) {   // RNA round in-register
    uint32_t o;
    asm("cvt.rna.tf32.f32 %0, %1;" : "=r"(o) : "f"(__uint_as_float(x)));
    return o;
}
__device__ __forceinline__ float gelu_new_f(float x) {
    float x3 = x * x * x;
    float inner = 0.7978845608028654f * (x + 0.044715f * x3);
    return 0.5f * x * (1.0f + tanhf(inner));
}
__device__ __forceinline__ void mma_tf32(float* c, const uint32_t* a, const uint32_t* b) {
    asm volatile(
        "mma.sync.aligned.m16n8k8.row.col.f32.tf32.tf32.f32 "
        "{%0,%1,%2,%3}, {%4,%5,%6,%7}, {%8,%9}, {%0,%1,%2,%3};"
        : "+f"(c[0]), "+f"(c[1]), "+f"(c[2]), "+f"(c[3])
        : "r"(a[0]), "r"(a[1]), "r"(a[2]), "r"(a[3]), "r"(b[0]), "r"(b[1]));
}
#define LDSM4(d, a) \
    asm volatile("ldmatrix.sync.aligned.m8n8.x4.shared.b16 {%0,%1,%2,%3}, [%4];" \
        : "=r"((d)[0]), "=r"((d)[1]), "=r"((d)[2]), "=r"((d)[3]) : "r"(a))

// ---------------- per-token rank-16 lora z -------------------------------------
// Z[t, e*16+r] = SCAL * x[t] . A[e,r], zero elsewhere. fp32 (GEMM rounds later).
template<int KD>
__global__ void lora_z_k(const float* __restrict__ X, const float* __restrict__ A,
                         const int* __restrict__ eidx, float* __restrict__ Z) {
    int t = blockIdx.x;
    int e = eidx[t];
    int lane = threadIdx.x & 31, w = threadIdx.x >> 5;
    if (threadIdx.x < ER) Z[t * ER + threadIdx.x] = 0.f;
    __syncthreads();
    const float* a = A + ((size_t)e * RRK + w) * KD;
    const float* x = X + (size_t)t * KD;
    float s = 0.f;
    for (int i = lane * 4; i < KD; i += 128) {
        float4 xv = *reinterpret_cast<const float4*>(x + i);
        float4 av = *reinterpret_cast<const float4*>(a + i);
        s += xv.x * av.x + xv.y * av.y + xv.z * av.z + xv.w * av.w;
    }
    #pragma unroll
    for (int o = 16; o; o >>= 1) s += __shfl_xor_sync(0xffffffffu, s, o);
    if (lane == 0) Z[t * ER + e * RRK + w] = SCAL * s;
}

// ---------------- tf32 GEMM: C[T,N] = [A0|AL] @ [W|BL]^T (+bias, opt gelu) ----
// Fragments loaded with ldmatrix.x4 from a 128B-block smem layout:
//   addr(m,k) = (m>>3)*1024 + (k>>2)*128 + (m&7)*16   (conflict-free)
// All operands rounded to tf32 (RNA) in-register right before mma.
template<int K0, bool GELU>
__global__ void __launch_bounds__(256, 2)
moe_gemm_k(const float* __restrict__ A0, const float* __restrict__ AL,
           const float* __restrict__ W,  const float* __restrict__ BL,
           const float* __restrict__ bias, float* __restrict__ C, int Nsz) {
    constexpr int NK = (K0 + ER) / BK;

    extern __shared__ __align__(1024) char smem[];
    const uint32_t smemU = smem_u32(smem);

    const int tid  = threadIdx.x;
    const int wid  = tid >> 5, lane = tid & 31;
    const int wm   = wid >> 2, wn = wid & 3;          // 2x4 warps, 64x32 each
    const int grp  = lane >> 2, tig = lane & 3;
    const int g8   = lane >> 3, r8 = lane & 7;
    const int lr   = tid >> 3, lc = tid & 7;          // loader: 32 rows x 8 chunks
    const int m0   = blockIdx.y * BM, n0 = blockIdx.x * BN;

    // ldmatrix lane bases (within stage 0)
    const uint32_t laneA = smemU + (uint32_t)(wm * 8192 + (g8 & 1) * 1024 + (g8 >> 1) * 128 + r8 * 16);
    const uint32_t laneB = smemU + (uint32_t)(ASZ + wn * 4096 + (g8 >> 1) * 1024 + (g8 & 1) * 128 + r8 * 16);

    float acc[4][4][4];
    #pragma unroll
    for (int i = 0; i < 4; i++)
        #pragma unroll
        for (int j = 0; j < 4; j++)
            #pragma unroll
            for (int c = 0; c < 4; c++) acc[i][j][c] = 0.f;

    auto load_stage = [&](int kt, int s) {
        uint32_t base = smemU + s * STAGE;
        int kk = kt * BK + lc * 4;
        #pragma unroll
        for (int p = 0; p < 4; p++) {
            int m = lr + p * 32;
            const float* gp = (kk < K0)
                ? A0 + (size_t)(m0 + m) * K0 + kk
                : AL + (size_t)(m0 + m) * ER + (kk - K0);
            cp16(base + (uint32_t)((m >> 3) * 1024 + lc * 128 + (m & 7) * 16), gp);
        }
        #pragma unroll
        for (int p = 0; p < 4; p++) {
            int n = lr + p * 32;
            const float* gp;
            if (kk < K0) gp = W + (size_t)(n0 + n) * K0 + kk;
            else {
                int j = kk - K0;
                gp = BL + ((size_t)(j >> 4) * Nsz + (n0 + n)) * RRK + (j & 15);
            }
            cp16(base + (uint32_t)(ASZ + (n >> 3) * 1024 + lc * 128 + (n & 7) * 16), gp);
        }
    };

    #pragma unroll
    for (int i = 0; i < NS; i++) {
        load_stage(i, i);
        asm volatile("cp.async.commit_group;" ::: "memory");
    }

    int s = 0;
    for (int kt = 0; kt < NK; ++kt) {
        asm volatile("cp.async.wait_group 2;" ::: "memory");
        __syncthreads();

        uint32_t sa = laneA + s * STAGE;
        uint32_t sb = laneB + s * STAGE;
        #pragma unroll
        for (int s4 = 0; s4 < 4; s4++) {
            uint32_t af[4][4], bf[2][4];
            #pragma unroll
            for (int i = 0; i < 4; i++) LDSM4(af[i], sa + i * 2048 + s4 * 256);
            #pragma unroll
            for (int p = 0; p < 2; p++)  LDSM4(bf[p], sb + p * 2048 + s4 * 256);
            #pragma unroll
            for (int i = 0; i < 4; i++)
                #pragma unroll
                for (int q = 0; q < 4; q++) af[i][q] = tf32b(af[i][q]);
            #pragma unroll
            for (int p = 0; p < 2; p++)
                #pragma unroll
                for (int q = 0; q < 4; q++) bf[p][q] = tf32b(bf[p][q]);
            #pragma unroll
            for (int i = 0; i < 4; i++)
                #pragma unroll
                for (int p = 0; p < 2; p++) {
                    mma_tf32(acc[i][2 * p + 0], af[i], &bf[p][0]);
                    mma_tf32(acc[i][2 * p + 1], af[i], &bf[p][2]);
                }
        }
        __syncthreads();
        if (kt + NS < NK) load_stage(kt + NS, s);
        asm volatile("cp.async.commit_group;" ::: "memory");
        s = (s == NS - 1) ? 0 : s + 1;
    }

    // epilogue
    #pragma unroll
    for (int i = 0; i < 4; i++) {
        int row0 = m0 + wm * 64 + i * 16 + grp;
        #pragma unroll
        for (int j = 0; j < 4; j++) {
            int col = n0 + wn * 32 + j * 8 + 2 * tig;
            float bv0 = bias[col], bv1 = bias[col + 1];
            float2 v0, v1;
            if (GELU) {
                v0.x = gelu_new_f(acc[i][j][0] + bv0);
                v0.y = gelu_new_f(acc[i][j][1] + bv1);
                v1.x = gelu_new_f(acc[i][j][2] + bv0);
                v1.y = gelu_new_f(acc[i][j][3] + bv1);
            } else {
                v0.x = acc[i][j][0] + bv0; v0.y = acc[i][j][1] + bv1;
                v1.x = acc[i][j][2] + bv0; v1.y = acc[i][j][3] + bv1;
            }
            *reinterpret_cast<float2*>(&C[(size_t)row0 * Nsz + col]) = v0;
            *reinterpret_cast<float2*>(&C[(size_t)(row0 + 8) * Nsz + col]) = v1;
        }
    }
}

// ---------------- launch --------------------------------------------------------
extern "C" void kernel_launch(void* const* d_in, const int* in_sizes, int n_in,
                              void* d_out, int out_size) {
    const float* x  = (const float*)d_in[0];
    const int*   ei = (const int*)  d_in[1];
    const float* W1 = (const float*)d_in[2];
    const float* b1 = (const float*)d_in[3];
    const float* A1 = (const float*)d_in[4];
    const float* B1 = (const float*)d_in[5];
    const float* W2 = (const float*)d_in[6];
    const float* b2 = (const float*)d_in[7];
    const float* A2 = (const float*)d_in[8];
    const float* B2 = (const float*)d_in[9];
    float* out = (float*)d_out;

    float *pY, *pZ1, *pZ2;
    cudaGetSymbolAddress((void**)&pY,  g_Y);
    cudaGetSymbolAddress((void**)&pZ1, g_Z1);
    cudaGetSymbolAddress((void**)&pZ2, g_Z2);

    cudaFuncSetAttribute(moe_gemm_k<DD, true>,
                         cudaFuncAttributeMaxDynamicSharedMemorySize, SMEMSZ);
    cudaFuncSetAttribute(moe_gemm_k<HH, false>,
                         cudaFuncAttributeMaxDynamicSharedMemorySize, SMEMSZ);

    lora_z_k<DD><<<TT, 512>>>(x, A1, ei, pZ1);

    moe_gemm_k<DD, true><<<dim3(HH / BN, TT / BM), 256, SMEMSZ>>>(
        x, pZ1, W1, B1, b1, pY, HH);

    lora_z_k<HH><<<TT, 512>>>(pY, A2, ei, pZ2);

    moe_gemm_k<HH, false><<<dim3(DD / BN, TT / BM), 256, SMEMSZ>>>(
        pY, pZ2, W2, B2, b2, out, DD);
}

// round 5
// speedup vs baseline: 1.0297x; 1.0297x over previous
#include <cuda_runtime.h>
#include <cstdint>

#define TT 4096
#define DD 2048
#define HH 8192
#define NE 8
#define RRK 16
#define ER 128
#define SCAL 2.0f

#define BM 128
#define BN 128
#define BK 32
#define NS 3
#define ASZ 16384                 // A tile bytes per stage
#define STAGE 32768               // (A + B) per stage
#define SMEMSZ (NS * STAGE)       // 96 KB -> 2 CTAs/SM

// ---------------- scratch (device globals) ------------------------------------
__device__ float g_W1r[(size_t)HH * DD];
__device__ float g_W2r[(size_t)DD * HH];
__device__ float g_B1r[(size_t)NE * HH * RRK];
__device__ float g_B2r[(size_t)NE * DD * RRK];
__device__ float g_Xr [(size_t)TT * DD];
__device__ float g_Y  [(size_t)TT * HH];
__device__ float g_Z1 [TT * ER];
__device__ float g_Z2 [TT * ER];

// ---------------- helpers ------------------------------------------------------
__device__ __forceinline__ float tf32r(float x) {
    uint32_t u;
    asm("cvt.rna.tf32.f32 %0, %1;" : "=r"(u) : "f"(x));
    return __uint_as_float(u);
}
__device__ __forceinline__ void cp16(uint32_t s, const void* g) {
    asm volatile("cp.async.ca.shared.global [%0], [%1], 16;" :: "r"(s), "l"(g));
}
__device__ __forceinline__ uint32_t smem_u32(const void* p) {
    uint32_t a;
    asm("{ .reg .u64 t; cvta.to.shared.u64 t, %1; cvt.u32.u64 %0, t; }" : "=r"(a) : "l"(p));
    return a;
}
__device__ __forceinline__ float gelu_new_f(float x) {
    float x3 = x * x * x;
    float inner = 0.7978845608028654f * (x + 0.044715f * x3);
    return 0.5f * x * (1.0f + tanhf(inner));
}
__device__ __forceinline__ void mma_tf32(float* c, const uint32_t* a, const uint32_t* b) {
    asm volatile(
        "mma.sync.aligned.m16n8k8.row.col.f32.tf32.tf32.f32 "
        "{%0,%1,%2,%3}, {%4,%5,%6,%7}, {%8,%9}, {%0,%1,%2,%3};"
        : "+f"(c[0]), "+f"(c[1]), "+f"(c[2]), "+f"(c[3])
        : "r"(a[0]), "r"(a[1]), "r"(a[2]), "r"(a[3]), "r"(b[0]), "r"(b[1]));
}
#define LDSM4(d, a) \
    asm volatile("ldmatrix.sync.aligned.m8n8.x4.shared.b16 {%0,%1,%2,%3}, [%4];" \
        : "=r"((d)[0]), "=r"((d)[1]), "=r"((d)[2]), "=r"((d)[3]) : "r"(a))

// ---------------- tf32 rounding copy -------------------------------------------
__global__ void round_tf32_k(float* __restrict__ dst, const float* __restrict__ src, int n4) {
    int i = blockIdx.x * blockDim.x + threadIdx.x;
    if (i < n4) {
        float4 v = reinterpret_cast<const float4*>(src)[i];
        v.x = tf32r(v.x); v.y = tf32r(v.y); v.z = tf32r(v.z); v.w = tf32r(v.w);
        reinterpret_cast<float4*>(dst)[i] = v;
    }
}

// ---------------- per-token rank-16 lora z (tf32-rounded output) ---------------
template<int KD>
__global__ void lora_z_k(const float* __restrict__ X, const float* __restrict__ A,
                         const int* __restrict__ eidx, float* __restrict__ Z) {
    int t = blockIdx.x;
    int e = eidx[t];
    int lane = threadIdx.x & 31, w = threadIdx.x >> 5;
    if (threadIdx.x < ER) Z[t * ER + threadIdx.x] = 0.f;
    __syncthreads();
    const float* a = A + ((size_t)e * RRK + w) * KD;
    const float* x = X + (size_t)t * KD;
    float s = 0.f;
    for (int i = lane * 4; i < KD; i += 128) {
        float4 xv = *reinterpret_cast<const float4*>(x + i);
        float4 av = *reinterpret_cast<const float4*>(a + i);
        s += xv.x * av.x + xv.y * av.y + xv.z * av.z + xv.w * av.w;
    }
    #pragma unroll
    for (int o = 16; o; o >>= 1) s += __shfl_xor_sync(0xffffffffu, s, o);
    if (lane == 0) Z[t * ER + e * RRK + w] = tf32r(SCAL * s);
}

// ---------------- tf32 GEMM: C[T,N] = [A0|AL] @ [W|BL]^T (+bias, opt gelu) ----
// Operands pre-rounded to tf32. ldmatrix.x4 fragments from 128B-block layout:
//   addr(m,k) = (m>>3)*1024 + (k>>2)*128 + (m&7)*16  (conflict-free)
// Register-level double-buffered fragments hide LDSM latency.
template<int K0, bool GELU>
__global__ void __launch_bounds__(256, 2)
moe_gemm_k(const float* __restrict__ A0, const float* __restrict__ AL,
           const float* __restrict__ W,  const float* __restrict__ BL,
           const float* __restrict__ bias, float* __restrict__ C, int Nsz) {
    constexpr int NK = (K0 + ER) / BK;

    extern __shared__ __align__(1024) char smem[];
    const uint32_t smemU = smem_u32(smem);

    const int tid  = threadIdx.x;
    const int wid  = tid >> 5, lane = tid & 31;
    const int wm   = wid >> 2, wn = wid & 3;          // 2x4 warps, 64x32 each
    const int grp  = lane >> 2, tig = lane & 3;
    const int g8   = lane >> 3, r8 = lane & 7;
    const int lr   = tid >> 3, lc = tid & 7;          // loader: 32 rows x 8 chunks
    const int m0   = blockIdx.y * BM, n0 = blockIdx.x * BN;

    const uint32_t laneA = smemU + (uint32_t)(wm * 8192 + (g8 & 1) * 1024 + (g8 >> 1) * 128 + r8 * 16);
    const uint32_t laneB = smemU + (uint32_t)(ASZ + wn * 4096 + (g8 >> 1) * 1024 + (g8 & 1) * 128 + r8 * 16);

    float acc[4][4][4];
    #pragma unroll
    for (int i = 0; i < 4; i++)
        #pragma unroll
        for (int j = 0; j < 4; j++)
            #pragma unroll
            for (int c = 0; c < 4; c++) acc[i][j][c] = 0.f;

    auto load_stage = [&](int kt, int s) {
        uint32_t base = smemU + s * STAGE;
        int kk = kt * BK + lc * 4;
        #pragma unroll
        for (int p = 0; p < 4; p++) {
            int m = lr + p * 32;
            const float* gp = (kk < K0)
                ? A0 + (size_t)(m0 + m) * K0 + kk
                : AL + (size_t)(m0 + m) * ER + (kk - K0);
            cp16(base + (uint32_t)((m >> 3) * 1024 + lc * 128 + (m & 7) * 16), gp);
        }
        #pragma unroll
        for (int p = 0; p < 4; p++) {
            int n = lr + p * 32;
            const float* gp;
            if (kk < K0) gp = W + (size_t)(n0 + n) * K0 + kk;
            else {
                int j = kk - K0;
                gp = BL + ((size_t)(j >> 4) * Nsz + (n0 + n)) * RRK + (j & 15);
            }
            cp16(base + (uint32_t)(ASZ + (n >> 3) * 1024 + lc * 128 + (n & 7) * 16), gp);
        }
    };

    #pragma unroll
    for (int i = 0; i < NS; i++) {
        load_stage(i, i);
        asm volatile("cp.async.commit_group;" ::: "memory");
    }

    uint32_t af[2][4][4], bf[2][2][4];
    int s = 0;
    for (int kt = 0; kt < NK; ++kt) {
        asm volatile("cp.async.wait_group 2;" ::: "memory");
        __syncthreads();

        uint32_t sa = laneA + s * STAGE;
        uint32_t sb = laneB + s * STAGE;

        // preload fragments for k-slice 0
        #pragma unroll
        for (int i = 0; i < 4; i++) LDSM4(af[0][i], sa + i * 2048);
        #pragma unroll
        for (int p = 0; p < 2; p++) LDSM4(bf[0][p], sb + p * 2048);

        #pragma unroll
        for (int s4 = 0; s4 < 4; s4++) {
            int cur = s4 & 1, nxt = cur ^ 1;
            if (s4 < 3) {
                #pragma unroll
                for (int i = 0; i < 4; i++) LDSM4(af[nxt][i], sa + i * 2048 + (s4 + 1) * 256);
                #pragma unroll
                for (int p = 0; p < 2; p++) LDSM4(bf[nxt][p], sb + p * 2048 + (s4 + 1) * 256);
            }
            #pragma unroll
            for (int i = 0; i < 4; i++)
                #pragma unroll
                for (int p = 0; p < 2; p++) {
                    mma_tf32(acc[i][2 * p + 0], af[cur][i], &bf[cur][p][0]);
                    mma_tf32(acc[i][2 * p + 1], af[cur][i], &bf[cur][p][2]);
                }
        }
        __syncthreads();
        if (kt + NS < NK) load_stage(kt + NS, s);
        asm volatile("cp.async.commit_group;" ::: "memory");
        s = (s == NS - 1) ? 0 : s + 1;
    }

    // epilogue (GELU path writes tf32-rounded Y for the next GEMM)
    #pragma unroll
    for (int i = 0; i < 4; i++) {
        int row0 = m0 + wm * 64 + i * 16 + grp;
        #pragma unroll
        for (int j = 0; j < 4; j++) {
            int col = n0 + wn * 32 + j * 8 + 2 * tig;
            float bv0 = bias[col], bv1 = bias[col + 1];
            float2 v0, v1;
            if (GELU) {
                v0.x = tf32r(gelu_new_f(acc[i][j][0] + bv0));
                v0.y = tf32r(gelu_new_f(acc[i][j][1] + bv1));
                v1.x = tf32r(gelu_new_f(acc[i][j][2] + bv0));
                v1.y = tf32r(gelu_new_f(acc[i][j][3] + bv1));
            } else {
                v0.x = acc[i][j][0] + bv0; v0.y = acc[i][j][1] + bv1;
                v1.x = acc[i][j][2] + bv0; v1.y = acc[i][j][3] + bv1;
            }
            *reinterpret_cast<float2*>(&C[(size_t)row0 * Nsz + col]) = v0;
            *reinterpret_cast<float2*>(&C[(size_t)(row0 + 8) * Nsz + col]) = v1;
        }
    }
}

// ---------------- launch --------------------------------------------------------
extern "C" void kernel_launch(void* const* d_in, const int* in_sizes, int n_in,
                              void* d_out, int out_size) {
    const float* x  = (const float*)d_in[0];
    const int*   ei = (const int*)  d_in[1];
    const float* W1 = (const float*)d_in[2];
    const float* b1 = (const float*)d_in[3];
    const float* A1 = (const float*)d_in[4];
    const float* B1 = (const float*)d_in[5];
    const float* W2 = (const float*)d_in[6];
    const float* b2 = (const float*)d_in[7];
    const float* A2 = (const float*)d_in[8];
    const float* B2 = (const float*)d_in[9];
    float* out = (float*)d_out;

    float *pW1r, *pW2r, *pB1r, *pB2r, *pXr, *pY, *pZ1, *pZ2;
    cudaGetSymbolAddress((void**)&pW1r, g_W1r);
    cudaGetSymbolAddress((void**)&pW2r, g_W2r);
    cudaGetSymbolAddress((void**)&pB1r, g_B1r);
    cudaGetSymbolAddress((void**)&pB2r, g_B2r);
    cudaGetSymbolAddress((void**)&pXr,  g_Xr);
    cudaGetSymbolAddress((void**)&pY,   g_Y);
    cudaGetSymbolAddress((void**)&pZ1,  g_Z1);
    cudaGetSymbolAddress((void**)&pZ2,  g_Z2);

    cudaFuncSetAttribute(moe_gemm_k<DD, true>,
                         cudaFuncAttributeMaxDynamicSharedMemorySize, SMEMSZ);
    cudaFuncSetAttribute(moe_gemm_k<HH, false>,
                         cudaFuncAttributeMaxDynamicSharedMemorySize, SMEMSZ);

    int n4;
    n4 = HH * DD / 4;        round_tf32_k<<<(n4 + 255) / 256, 256>>>(pW1r, W1, n4);
    n4 = DD * HH / 4;        round_tf32_k<<<(n4 + 255) / 256, 256>>>(pW2r, W2, n4);
    n4 = NE * HH * RRK / 4;  round_tf32_k<<<(n4 + 255) / 256, 256>>>(pB1r, B1, n4);
    n4 = NE * DD * RRK / 4;  round_tf32_k<<<(n4 + 255) / 256, 256>>>(pB2r, B2, n4);
    n4 = TT * DD / 4;        round_tf32_k<<<(n4 + 255) / 256, 256>>>(pXr,  x,  n4);

    lora_z_k<DD><<<TT, 512>>>(x, A1, ei, pZ1);

    moe_gemm_k<DD, true><<<dim3(HH / BN, TT / BM), 256, SMEMSZ>>>(
        pXr, pZ1, pW1r, pB1r, b1, pY, HH);

    lora_z_k<HH><<<TT, 512>>>(pY, A2, ei, pZ2);

    moe_gemm_k<HH, false><<<dim3(DD / BN, TT / BM), 256, SMEMSZ>>>(
        pY, pZ2, pW2r, pB2r, b2, out, DD);
}

// round 6
// speedup vs baseline: 1.1625x; 1.1290x over previous
#include <cuda_runtime.h>
#include <cstdint>

#define TT 4096
#define DD 2048
#define HH 8192
#define NE 8
#define RRK 16
#define ER 128
#define SCAL 2.0f

// ---------------- scratch (device globals; no allocation allowed) -------------
__device__ float g_W1r[(size_t)HH * DD];      // tf32-rounded W1  [H,D]
__device__ float g_W2r[(size_t)DD * HH];      // tf32-rounded W2  [D,H]
__device__ float g_B1r[(size_t)NE * HH * RRK];// tf32-rounded B1  [E,H,R]
__device__ float g_B2r[(size_t)NE * DD * RRK];// tf32-rounded B2  [E,D,R]
__device__ float g_A1r[(size_t)ER * DD];      // tf32-rounded A1  [128,D]
__device__ float g_A2r[(size_t)ER * HH];      // tf32-rounded A2  [128,H]
__device__ float g_Xr [(size_t)TT * DD];      // tf32-rounded x   [T,D]
__device__ float g_Y  [(size_t)TT * HH];      // gelu output (tf32-rounded) [T,H]
__device__ float g_Z1 [TT * ER];              // masked lora z for fc1 [T,128]
__device__ float g_Z2 [TT * ER];              // masked lora z for fc2 [T,128]

// ---------------- helpers ----------------------------------------------------
__device__ __forceinline__ float tf32r(float x) {
    uint32_t u;
    asm("cvt.rna.tf32.f32 %0, %1;" : "=r"(u) : "f"(x));
    return __uint_as_float(u);
}

__device__ __forceinline__ void cp16(uint32_t s, const void* g) {
    asm volatile("cp.async.ca.shared.global [%0], [%1], 16;" :: "r"(s), "l"(g));
}

__device__ __forceinline__ void mma_tf32(float* c, const uint32_t* a, const uint32_t* b) {
    asm volatile(
        "mma.sync.aligned.m16n8k8.row.col.f32.tf32.tf32.f32 "
        "{%0,%1,%2,%3}, {%4,%5,%6,%7}, {%8,%9}, {%0,%1,%2,%3};"
        : "+f"(c[0]), "+f"(c[1]), "+f"(c[2]), "+f"(c[3])
        : "r"(a[0]), "r"(a[1]), "r"(a[2]), "r"(a[3]), "r"(b[0]), "r"(b[1]));
}

__device__ __forceinline__ float gelu_new_f(float x) {
    float x3 = x * x * x;
    float inner = 0.7978845608028654f * (x + 0.044715f * x3);
    return 0.5f * x * (1.0f + tanhf(inner));
}

// ---------------- tf32 rounding copy -----------------------------------------
__global__ void round_tf32_k(float* __restrict__ dst, const float* __restrict__ src, int n4) {
    int i = blockIdx.x * blockDim.x + threadIdx.x;
    if (i < n4) {
        float4 v = reinterpret_cast<const float4*>(src)[i];
        v.x = tf32r(v.x); v.y = tf32r(v.y); v.z = tf32r(v.z); v.w = tf32r(v.w);
        reinterpret_cast<float4*>(dst)[i] = v;
    }
}

// ---------------- fused GEMM (R0-proven core) ---------------------------------
// C[T,N] = [A0|AL] @ [W|BL]^T
// TAIL:  append the 128-wide lora K-tail (AL[T,128], BL[E,N,16]).
// GELU:  bias + gelu_new, tf32-rounded output (fc1).
// MASK:  Z-GEMM epilogue: C[t,j] = (j>>4 == eidx[t]) ? tf32r(SCAL*acc) : 0.
// !MASK: bias added.
#define BM 128
#define BN 128
#define BK 32
#define SKW 36          // smem row stride in words (conflict-free: 4*grp+tig)
#define SBUF 4608       // 128*36 words per buffer

template<int K0, bool TAIL, bool GELU, bool MASK>
__global__ void __launch_bounds__(256, 2)
moe_gemm_k(const float* __restrict__ A0, const float* __restrict__ AL,
           const float* __restrict__ W,  const float* __restrict__ BL,
           const float* __restrict__ bias, const int* __restrict__ eidx,
           float* __restrict__ C, int Nsz) {
    extern __shared__ float smem[];           // [As0|As1|Bs0|Bs1], 73728 B
    const int NK = (K0 + (TAIL ? ER : 0)) / BK;
    const int m0 = blockIdx.y * BM, n0 = blockIdx.x * BN;
    const int tid  = threadIdx.x;
    const int lr   = tid >> 3, lc = tid & 7;  // loader: 32 rows x 8 float4-cols
    const int warp = tid >> 5, wm = warp >> 2, wn = warp & 3;
    const int lane = tid & 31, grp = lane >> 2, tig = lane & 3;

    float acc[4][4][4];
    #pragma unroll
    for (int i = 0; i < 4; i++)
        #pragma unroll
        for (int j = 0; j < 4; j++)
            #pragma unroll
            for (int c = 0; c < 4; c++) acc[i][j][c] = 0.f;

    uint32_t sA = (uint32_t)__cvta_generic_to_shared(smem);
    uint32_t sB = sA + 2 * SBUF * 4;

    auto load_tiles = [&](int kt, int buf) {
        int kk = kt * BK + 4 * lc;
        #pragma unroll
        for (int p = 0; p < 4; p++) {
            int row = lr + p * 32;
            const float* gp = (!TAIL || kk < K0)
                ? A0 + (size_t)(m0 + row) * K0 + kk
                : AL + (size_t)(m0 + row) * ER + (kk - K0);
            cp16(sA + (uint32_t)(buf * SBUF + row * SKW + 4 * lc) * 4, gp);
        }
        #pragma unroll
        for (int p = 0; p < 4; p++) {
            int nr = lr + p * 32;
            const float* gp;
            if (!TAIL || kk < K0) {
                gp = W + (size_t)(n0 + nr) * K0 + kk;
            } else {
                int j = kk - K0;                       // j in [0,128): e=j>>4, r=j&15
                gp = BL + ((size_t)(j >> 4) * Nsz + (n0 + nr)) * RRK + (j & 15);
            }
            cp16(sB + (uint32_t)(buf * SBUF + nr * SKW + 4 * lc) * 4, gp);
        }
    };

    load_tiles(0, 0);
    asm volatile("cp.async.commit_group;");
    load_tiles(1, 1);
    asm volatile("cp.async.commit_group;");

    for (int kt = 0; kt < NK; ++kt) {
        asm volatile("cp.async.wait_group 1;");
        __syncthreads();
        int buf = kt & 1;
        const float* As = smem + buf * SBUF;
        const float* Bs = smem + 2 * SBUF + buf * SBUF;
        #pragma unroll
        for (int s = 0; s < 4; s++) {
            uint32_t af[4][4], bf[4][2];
            int k = s * 8 + tig;
            #pragma unroll
            for (int i = 0; i < 4; i++) {
                int m = wm * 64 + i * 16 + grp;
                af[i][0] = __float_as_uint(As[m * SKW + k]);
                af[i][1] = __float_as_uint(As[(m + 8) * SKW + k]);
                af[i][2] = __float_as_uint(As[m * SKW + k + 4]);
                af[i][3] = __float_as_uint(As[(m + 8) * SKW + k + 4]);
            }
            #pragma unroll
            for (int j = 0; j < 4; j++) {
                int n = wn * 32 + j * 8 + grp;
                bf[j][0] = __float_as_uint(Bs[n * SKW + k]);
                bf[j][1] = __float_as_uint(Bs[n * SKW + k + 4]);
            }
            #pragma unroll
            for (int i = 0; i < 4; i++)
                #pragma unroll
                for (int j = 0; j < 4; j++)
                    mma_tf32(acc[i][j], af[i], bf[j]);
        }
        __syncthreads();
        if (kt + 2 < NK) load_tiles(kt + 2, buf);
        asm volatile("cp.async.commit_group;");
    }

    // epilogue
    #pragma unroll
    for (int i = 0; i < 4; i++) {
        int t0 = m0 + wm * 64 + i * 16 + grp;
        int e0 = 0, e1 = 0;
        if (MASK) { e0 = eidx[t0]; e1 = eidx[t0 + 8]; }
        #pragma unroll
        for (int j = 0; j < 4; j++) {
            int n = n0 + wn * 32 + j * 8 + 2 * tig;
            float2 v0, v1;
            if (MASK) {
                bool hit0 = ((n >> 4) == e0), hit1 = ((n >> 4) == e1);
                v0.x = hit0 ? tf32r(SCAL * acc[i][j][0]) : 0.f;
                v0.y = hit0 ? tf32r(SCAL * acc[i][j][1]) : 0.f;
                v1.x = hit1 ? tf32r(SCAL * acc[i][j][2]) : 0.f;
                v1.y = hit1 ? tf32r(SCAL * acc[i][j][3]) : 0.f;
            } else {
                float bv0 = bias[n], bv1 = bias[n + 1];
                if (GELU) {
                    v0.x = tf32r(gelu_new_f(acc[i][j][0] + bv0));
                    v0.y = tf32r(gelu_new_f(acc[i][j][1] + bv1));
                    v1.x = tf32r(gelu_new_f(acc[i][j][2] + bv0));
                    v1.y = tf32r(gelu_new_f(acc[i][j][3] + bv1));
                } else {
                    v0.x = acc[i][j][0] + bv0; v0.y = acc[i][j][1] + bv1;
                    v1.x = acc[i][j][2] + bv0; v1.y = acc[i][j][3] + bv1;
                }
            }
            *reinterpret_cast<float2*>(&C[(size_t)t0 * Nsz + n]) = v0;
            *reinterpret_cast<float2*>(&C[(size_t)(t0 + 8) * Nsz + n]) = v1;
        }
    }
}

// ---------------- launch ------------------------------------------------------
extern "C" void kernel_launch(void* const* d_in, const int* in_sizes, int n_in,
                              void* d_out, int out_size) {
    const float* x  = (const float*)d_in[0];
    const int*   ei = (const int*)  d_in[1];
    const float* W1 = (const float*)d_in[2];
    const float* b1 = (const float*)d_in[3];
    const float* A1 = (const float*)d_in[4];
    const float* B1 = (const float*)d_in[5];
    const float* W2 = (const float*)d_in[6];
    const float* b2 = (const float*)d_in[7];
    const float* A2 = (const float*)d_in[8];
    const float* B2 = (const float*)d_in[9];
    float* out = (float*)d_out;

    float *pW1r, *pW2r, *pB1r, *pB2r, *pA1r, *pA2r, *pXr, *pY, *pZ1, *pZ2;
    cudaGetSymbolAddress((void**)&pW1r, g_W1r);
    cudaGetSymbolAddress((void**)&pW2r, g_W2r);
    cudaGetSymbolAddress((void**)&pB1r, g_B1r);
    cudaGetSymbolAddress((void**)&pB2r, g_B2r);
    cudaGetSymbolAddress((void**)&pA1r, g_A1r);
    cudaGetSymbolAddress((void**)&pA2r, g_A2r);
    cudaGetSymbolAddress((void**)&pXr,  g_Xr);
    cudaGetSymbolAddress((void**)&pY,   g_Y);
    cudaGetSymbolAddress((void**)&pZ1,  g_Z1);
    cudaGetSymbolAddress((void**)&pZ2,  g_Z2);

    cudaFuncSetAttribute(moe_gemm_k<DD, true,  true,  false>,
                         cudaFuncAttributeMaxDynamicSharedMemorySize, 73728);
    cudaFuncSetAttribute(moe_gemm_k<HH, true,  false, false>,
                         cudaFuncAttributeMaxDynamicSharedMemorySize, 73728);
    cudaFuncSetAttribute(moe_gemm_k<DD, false, false, true>,
                         cudaFuncAttributeMaxDynamicSharedMemorySize, 73728);
    cudaFuncSetAttribute(moe_gemm_k<HH, false, false, true>,
                         cudaFuncAttributeMaxDynamicSharedMemorySize, 73728);

    int n4;
    // layer-1 prep (launches 0-3)
    n4 = HH * DD / 4;        round_tf32_k<<<(n4 + 255) / 256, 256>>>(pW1r, W1, n4);
    n4 = NE * HH * RRK / 4;  round_tf32_k<<<(n4 + 255) / 256, 256>>>(pB1r, B1, n4);
    n4 = TT * DD / 4;        round_tf32_k<<<(n4 + 255) / 256, 256>>>(pXr,  x,  n4);
    n4 = ER * DD / 4;        round_tf32_k<<<(n4 + 255) / 256, 256>>>(pA1r, A1, n4);

    // launch 4: dense Z1 = mask(SCAL * X @ A1^T)
    moe_gemm_k<DD, false, false, true><<<dim3(1, TT / BM), 256, 73728>>>(
        pXr, nullptr, pA1r, nullptr, nullptr, ei, pZ1, ER);

    // launch 5 (ncu target): fc1  Y = tf32(gelu(X@W1^T + b1 + Z1@B1^T))
    moe_gemm_k<DD, true, true, false><<<dim3(HH / BN, TT / BM), 256, 73728>>>(
        pXr, pZ1, pW1r, pB1r, b1, nullptr, pY, HH);

    // layer-2 prep
    n4 = DD * HH / 4;        round_tf32_k<<<(n4 + 255) / 256, 256>>>(pW2r, W2, n4);
    n4 = NE * DD * RRK / 4;  round_tf32_k<<<(n4 + 255) / 256, 256>>>(pB2r, B2, n4);
    n4 = ER * HH / 4;        round_tf32_k<<<(n4 + 255) / 256, 256>>>(pA2r, A2, n4);

    // dense Z2 = mask(SCAL * Y @ A2^T)
    moe_gemm_k<HH, false, false, true><<<dim3(1, TT / BM), 256, 73728>>>(
        pY, nullptr, pA2r, nullptr, nullptr, ei, pZ2, ER);

    // fc2: out = Y@W2^T + b2 + Z2@B2^T
    moe_gemm_k<HH, true, false, false><<<dim3(DD / BN, TT / BM), 256, 73728>>>(
        pY, pZ2, pW2r, pB2r, b2, nullptr, out, DD);
}

// round 7
// speedup vs baseline: 2.2428x; 1.9293x over previous
#include <cuda_runtime.h>
#include <cuda_fp16.h>
#include <cstdint>

#define TT 4096
#define DD 2048
#define HH 8192
#define NE 8
#define RRK 16
#define ER 128
#define SCAL 2.0f

#define BM 128
#define BN 128
#define BK 32                 // 32 halfs of K per tile
#define RS 20                 // smem row stride in 32-bit words (40 halfs) — conflict-free
#define TILEB (BM * RS * 4)   // 10240 B per operand tile
#define SMEMSZ (4 * TILEB)    // 2 operands x 2 buffers = 40960 B

// ---------------- scratch (device globals) ------------------------------------
__device__ __half g_W1h[(size_t)HH * DD];
__device__ __half g_W2h[(size_t)DD * HH];
__device__ __half g_B1h[(size_t)NE * HH * RRK];
__device__ __half g_B2h[(size_t)NE * DD * RRK];
__device__ __half g_A1h[(size_t)ER * DD];
__device__ __half g_A2h[(size_t)ER * HH];
__device__ __half g_Xh [(size_t)TT * DD];
__device__ __half g_Yh [(size_t)TT * HH];
__device__ __half g_Z1h[TT * ER];
__device__ __half g_Z2h[TT * ER];

// ---------------- helpers ------------------------------------------------------
__device__ __forceinline__ void cp16(uint32_t s, const void* g) {
    asm volatile("cp.async.ca.shared.global [%0], [%1], 16;" :: "r"(s), "l"(g));
}
__device__ __forceinline__ float gelu_new_f(float x) {
    float x3 = x * x * x;
    float inner = 0.7978845608028654f * (x + 0.044715f * x3);
    return 0.5f * x * (1.0f + tanhf(inner));
}
__device__ __forceinline__ void mma_f16(float* c, const uint32_t* a, const uint32_t* b) {
    asm volatile(
        "mma.sync.aligned.m16n8k16.row.col.f32.f16.f16.f32 "
        "{%0,%1,%2,%3}, {%4,%5,%6,%7}, {%8,%9}, {%0,%1,%2,%3};"
        : "+f"(c[0]), "+f"(c[1]), "+f"(c[2]), "+f"(c[3])
        : "r"(a[0]), "r"(a[1]), "r"(a[2]), "r"(a[3]), "r"(b[0]), "r"(b[1]));
}

// ---------------- fp32 -> fp16 convert ----------------------------------------
__global__ void tohalf_k(__half2* __restrict__ dst, const float4* __restrict__ src, int n4) {
    int i = blockIdx.x * blockDim.x + threadIdx.x;
    if (i < n4) {
        float4 v = src[i];
        dst[2 * i + 0] = __floats2half2_rn(v.x, v.y);
        dst[2 * i + 1] = __floats2half2_rn(v.z, v.w);
    }
}

// ---------------- fp16 GEMM: C[T,N] = [A0|AL] @ [W|BL]^T -----------------------
// A0:[T,K0] half, AL:[T,128] half; W:[N,K0] half row-major; BL:[E,N,16] half.
// MASK: Z epilogue (mask by expert, *SCAL, half out). GELU: bias+gelu, half out.
// else: bias, fp32 out.
template<int K0, bool TAIL, bool GELU, bool MASK>
__global__ void __launch_bounds__(256, 2)
moe_gemm_h(const __half* __restrict__ A0, const __half* __restrict__ AL,
           const __half* __restrict__ W,  const __half* __restrict__ BL,
           const float* __restrict__ bias, const int* __restrict__ eidx,
           void* __restrict__ Cout, int Nsz) {
    extern __shared__ __align__(128) char smem[];
    const int NK = (K0 + (TAIL ? ER : 0)) / BK;
    const int m0 = blockIdx.y * BM, n0 = blockIdx.x * BN;
    const int tid  = threadIdx.x;
    const int warp = tid >> 5, wm = warp >> 2, wn = warp & 3;   // 2x4 warps, 64x32
    const int lane = tid & 31, grp = lane >> 2, tig = lane & 3;
    const int lrow = tid >> 1, lch = tid & 1;                    // loader: 128 rows x 2

    float acc[4][4][4];
    #pragma unroll
    for (int i = 0; i < 4; i++)
        #pragma unroll
        for (int j = 0; j < 4; j++)
            #pragma unroll
            for (int c = 0; c < 4; c++) acc[i][j][c] = 0.f;

    const uint32_t sA = (uint32_t)__cvta_generic_to_shared(smem);
    const uint32_t sB = sA + 2 * TILEB;

    auto load_tiles = [&](int kt, int buf) {
        #pragma unroll
        for (int q = 0; q < 2; q++) {
            int c  = lch + 2 * q;                      // 16B chunk 0..3 within row
            int kk = kt * BK + c * 8;
            const __half* gp = (!TAIL || kk < K0)
                ? A0 + (size_t)(m0 + lrow) * K0 + kk
                : AL + (size_t)(m0 + lrow) * ER + (kk - K0);
            cp16(sA + (uint32_t)(buf * TILEB + lrow * 80 + c * 16), gp);
            const __half* gq;
            if (!TAIL || kk < K0) {
                gq = W + (size_t)(n0 + lrow) * K0 + kk;
            } else {
                int j = kk - K0;                       // e = j>>4, r = j&15 (j%8==0)
                gq = BL + ((size_t)(j >> 4) * Nsz + (n0 + lrow)) * RRK + (j & 15);
            }
            cp16(sB + (uint32_t)(buf * TILEB + lrow * 80 + c * 16), gq);
        }
    };

    load_tiles(0, 0);
    asm volatile("cp.async.commit_group;");
    load_tiles(1, 1);
    asm volatile("cp.async.commit_group;");

    for (int kt = 0; kt < NK; ++kt) {
        asm volatile("cp.async.wait_group 1;");
        __syncthreads();
        int buf = kt & 1;
        const uint32_t* As = (const uint32_t*)(smem + buf * TILEB);
        const uint32_t* Bs = (const uint32_t*)(smem + 2 * TILEB + buf * TILEB);
        #pragma unroll
        for (int s2 = 0; s2 < 2; s2++) {               // two k16 slices
            uint32_t af[4][4], bf[4][2];
            int kw = s2 * 8 + tig;
            #pragma unroll
            for (int i = 0; i < 4; i++) {
                int m = wm * 64 + i * 16 + grp;
                af[i][0] = As[m * RS + kw];
                af[i][1] = As[(m + 8) * RS + kw];
                af[i][2] = As[m * RS + kw + 4];
                af[i][3] = As[(m + 8) * RS + kw + 4];
            }
            #pragma unroll
            for (int j = 0; j < 4; j++) {
                int n = wn * 32 + j * 8 + grp;
                bf[j][0] = Bs[n * RS + kw];
                bf[j][1] = Bs[n * RS + kw + 4];
            }
            #pragma unroll
            for (int i = 0; i < 4; i++)
                #pragma unroll
                for (int j = 0; j < 4; j++)
                    mma_f16(acc[i][j], af[i], bf[j]);
        }
        __syncthreads();
        if (kt + 2 < NK) load_tiles(kt + 2, buf);
        asm volatile("cp.async.commit_group;");
    }

    // epilogue: thread owns C[row][2tig,2tig+1] and C[row+8][...]
    #pragma unroll
    for (int i = 0; i < 4; i++) {
        int t0 = m0 + wm * 64 + i * 16 + grp;
        int e0 = 0, e1 = 0;
        if (MASK) { e0 = eidx[t0]; e1 = eidx[t0 + 8]; }
        #pragma unroll
        for (int j = 0; j < 4; j++) {
            int n = n0 + wn * 32 + j * 8 + 2 * tig;
            if (MASK) {
                __half2* C = (__half2*)Cout;
                bool h0 = ((n >> 4) == e0), h1 = ((n >> 4) == e1);
                __half2 z = __floats2half2_rn(0.f, 0.f);
                C[((size_t)t0 * Nsz + n) >> 1] =
                    h0 ? __floats2half2_rn(SCAL * acc[i][j][0], SCAL * acc[i][j][1]) : z;
                C[((size_t)(t0 + 8) * Nsz + n) >> 1] =
                    h1 ? __floats2half2_rn(SCAL * acc[i][j][2], SCAL * acc[i][j][3]) : z;
            } else if (GELU) {
                __half2* C = (__half2*)Cout;
                float bv0 = bias[n], bv1 = bias[n + 1];
                C[((size_t)t0 * Nsz + n) >> 1] = __floats2half2_rn(
                    gelu_new_f(acc[i][j][0] + bv0), gelu_new_f(acc[i][j][1] + bv1));
                C[((size_t)(t0 + 8) * Nsz + n) >> 1] = __floats2half2_rn(
                    gelu_new_f(acc[i][j][2] + bv0), gelu_new_f(acc[i][j][3] + bv1));
            } else {
                float* C = (float*)Cout;
                float bv0 = bias[n], bv1 = bias[n + 1];
                float2 v0 = {acc[i][j][0] + bv0, acc[i][j][1] + bv1};
                float2 v1 = {acc[i][j][2] + bv0, acc[i][j][3] + bv1};
                *reinterpret_cast<float2*>(&C[(size_t)t0 * Nsz + n]) = v0;
                *reinterpret_cast<float2*>(&C[(size_t)(t0 + 8) * Nsz + n]) = v1;
            }
        }
    }
}

// ---------------- launch --------------------------------------------------------
extern "C" void kernel_launch(void* const* d_in, const int* in_sizes, int n_in,
                              void* d_out, int out_size) {
    const float* x  = (const float*)d_in[0];
    const int*   ei = (const int*)  d_in[1];
    const float* W1 = (const float*)d_in[2];
    const float* b1 = (const float*)d_in[3];
    const float* A1 = (const float*)d_in[4];
    const float* B1 = (const float*)d_in[5];
    const float* W2 = (const float*)d_in[6];
    const float* b2 = (const float*)d_in[7];
    const float* A2 = (const float*)d_in[8];
    const float* B2 = (const float*)d_in[9];
    float* out = (float*)d_out;

    __half *pW1, *pW2, *pB1, *pB2, *pA1, *pA2, *pX, *pY, *pZ1, *pZ2;
    cudaGetSymbolAddress((void**)&pW1, g_W1h);
    cudaGetSymbolAddress((void**)&pW2, g_W2h);
    cudaGetSymbolAddress((void**)&pB1, g_B1h);
    cudaGetSymbolAddress((void**)&pB2, g_B2h);
    cudaGetSymbolAddress((void**)&pA1, g_A1h);
    cudaGetSymbolAddress((void**)&pA2, g_A2h);
    cudaGetSymbolAddress((void**)&pX,  g_Xh);
    cudaGetSymbolAddress((void**)&pY,  g_Yh);
    cudaGetSymbolAddress((void**)&pZ1, g_Z1h);
    cudaGetSymbolAddress((void**)&pZ2, g_Z2h);

    cudaFuncSetAttribute(moe_gemm_h<DD, true,  true,  false>,
                         cudaFuncAttributeMaxDynamicSharedMemorySize, SMEMSZ);
    cudaFuncSetAttribute(moe_gemm_h<HH, true,  false, false>,
                         cudaFuncAttributeMaxDynamicSharedMemorySize, SMEMSZ);
    cudaFuncSetAttribute(moe_gemm_h<DD, false, false, true>,
                         cudaFuncAttributeMaxDynamicSharedMemorySize, SMEMSZ);
    cudaFuncSetAttribute(moe_gemm_h<HH, false, false, true>,
                         cudaFuncAttributeMaxDynamicSharedMemorySize, SMEMSZ);

    int n4;
    // layer-1 prep (launches 0-3)
    n4 = HH * DD / 4;        tohalf_k<<<(n4 + 255) / 256, 256>>>((__half2*)pW1, (const float4*)W1, n4);
    n4 = NE * HH * RRK / 4;  tohalf_k<<<(n4 + 255) / 256, 256>>>((__half2*)pB1, (const float4*)B1, n4);
    n4 = TT * DD / 4;        tohalf_k<<<(n4 + 255) / 256, 256>>>((__half2*)pX,  (const float4*)x,  n4);
    n4 = ER * DD / 4;        tohalf_k<<<(n4 + 255) / 256, 256>>>((__half2*)pA1, (const float4*)A1, n4);

    // launch 4: Z1 = mask(SCAL * X @ A1^T)  -> half
    moe_gemm_h<DD, false, false, true><<<dim3(1, TT / BM), 256, SMEMSZ>>>(
        pX, nullptr, pA1, nullptr, nullptr, ei, pZ1, ER);

    // launch 5 (ncu target): fc1  Y = half(gelu(X@W1^T + b1 + Z1@B1^T))
    moe_gemm_h<DD, true, true, false><<<dim3(HH / BN, TT / BM), 256, SMEMSZ>>>(
        pX, pZ1, pW1, pB1, b1, nullptr, pY, HH);

    // layer-2 prep
    n4 = DD * HH / 4;        tohalf_k<<<(n4 + 255) / 256, 256>>>((__half2*)pW2, (const float4*)W2, n4);
    n4 = NE * DD * RRK / 4;  tohalf_k<<<(n4 + 255) / 256, 256>>>((__half2*)pB2, (const float4*)B2, n4);
    n4 = ER * HH / 4;        tohalf_k<<<(n4 + 255) / 256, 256>>>((__half2*)pA2, (const float4*)A2, n4);

    // Z2 = mask(SCAL * Y @ A2^T) -> half
    moe_gemm_h<HH, false, false, true><<<dim3(1, TT / BM), 256, SMEMSZ>>>(
        pY, nullptr, pA2, nullptr, nullptr, ei, pZ2, ER);

    // fc2: out = Y@W2^T + b2 + Z2@B2^T  (fp32 out)
    moe_gemm_h<HH, true, false, false><<<dim3(DD / BN, TT / BM), 256, SMEMSZ>>>(
        pY, pZ2, pW2, pB2, b2, nullptr, out, DD);
}

// round 8
// speedup vs baseline: 2.3377x; 1.0423x over previous
#include <cuda_runtime.h>
#include <cuda_fp16.h>
#include <cstdint>

#define TT 4096
#define DD 2048
#define HH 8192
#define NE 8
#define RRK 16
#define ER 128
#define SCAL 2.0f

#define BM 128
#define BN 128
#define BK 32                 // 32 halfs of K per tile
#define NS 3
#define RS 20                 // smem row stride in 32-bit words (40 halfs) — conflict-free
#define TILEB (BM * RS * 4)   // 10240 B per operand tile
#define SMEMSZ (NS * 2 * TILEB) // 61440 B -> 2 CTAs/SM

// ---------------- scratch (device globals) ------------------------------------
__device__ __half g_W1h[(size_t)HH * DD];
__device__ __half g_W2h[(size_t)DD * HH];
__device__ __half g_B1h[(size_t)NE * HH * RRK];
__device__ __half g_B2h[(size_t)NE * DD * RRK];
__device__ __half g_A1h[(size_t)ER * DD];
__device__ __half g_A2h[(size_t)ER * HH];
__device__ __half g_Xh [(size_t)TT * DD];
__device__ __half g_Yh [(size_t)TT * HH];
__device__ __half g_Z1h[TT * ER];
__device__ __half g_Z2h[TT * ER];

// ---------------- helpers ------------------------------------------------------
__device__ __forceinline__ void cp16(uint32_t s, const void* g) {
    asm volatile("cp.async.cg.shared.global [%0], [%1], 16;" :: "r"(s), "l"(g));
}
__device__ __forceinline__ float gelu_new_f(float x) {
    float x3 = x * x * x;
    float inner = 0.7978845608028654f * (x + 0.044715f * x3);
    return 0.5f * x * (1.0f + tanhf(inner));
}
__device__ __forceinline__ void mma_f16(float* c, const uint32_t* a, const uint32_t* b) {
    asm volatile(
        "mma.sync.aligned.m16n8k16.row.col.f32.f16.f16.f32 "
        "{%0,%1,%2,%3}, {%4,%5,%6,%7}, {%8,%9}, {%0,%1,%2,%3};"
        : "+f"(c[0]), "+f"(c[1]), "+f"(c[2]), "+f"(c[3])
        : "r"(a[0]), "r"(a[1]), "r"(a[2]), "r"(a[3]), "r"(b[0]), "r"(b[1]));
}

// ---------------- fp32 -> fp16 convert ----------------------------------------
__global__ void tohalf_k(__half2* __restrict__ dst, const float4* __restrict__ src, int n4) {
    int i = blockIdx.x * blockDim.x + threadIdx.x;
    if (i < n4) {
        float4 v = src[i];
        dst[2 * i + 0] = __floats2half2_rn(v.x, v.y);
        dst[2 * i + 1] = __floats2half2_rn(v.z, v.w);
    }
}

// ---------------- fp16 GEMM: C[T,N] = [A0|AL] @ [W|BL]^T -----------------------
// 3-stage cp.async ring, single __syncthreads per ktile.
template<int K0, bool TAIL, bool GELU, bool MASK>
__global__ void __launch_bounds__(256, 2)
moe_gemm_h(const __half* __restrict__ A0, const __half* __restrict__ AL,
           const __half* __restrict__ W,  const __half* __restrict__ BL,
           const float* __restrict__ bias, const int* __restrict__ eidx,
           void* __restrict__ Cout, int Nsz) {
    extern __shared__ __align__(128) char smem[];
    const int NK = (K0 + (TAIL ? ER : 0)) / BK;
    const int m0 = blockIdx.y * BM, n0 = blockIdx.x * BN;
    const int tid  = threadIdx.x;
    const int warp = tid >> 5, wm = warp >> 2, wn = warp & 3;   // 2x4 warps, 64x32
    const int lane = tid & 31, grp = lane >> 2, tig = lane & 3;
    const int lrow = tid >> 1, lch = tid & 1;                    // loader: 128 rows x 2

    float acc[4][4][4];
    #pragma unroll
    for (int i = 0; i < 4; i++)
        #pragma unroll
        for (int j = 0; j < 4; j++)
            #pragma unroll
            for (int c = 0; c < 4; c++) acc[i][j][c] = 0.f;

    const uint32_t sA = (uint32_t)__cvta_generic_to_shared(smem);
    const uint32_t sB = sA + NS * TILEB;

    auto load_tiles = [&](int kt, int buf) {
        #pragma unroll
        for (int q = 0; q < 2; q++) {
            int c  = lch + 2 * q;                      // 16B chunk 0..3 within row
            int kk = kt * BK + c * 8;
            const __half* gp = (!TAIL || kk < K0)
                ? A0 + (size_t)(m0 + lrow) * K0 + kk
                : AL + (size_t)(m0 + lrow) * ER + (kk - K0);
            cp16(sA + (uint32_t)(buf * TILEB + lrow * 80 + c * 16), gp);
            const __half* gq;
            if (!TAIL || kk < K0) {
                gq = W + (size_t)(n0 + lrow) * K0 + kk;
            } else {
                int j = kk - K0;                       // e = j>>4, r = j&15
                gq = BL + ((size_t)(j >> 4) * Nsz + (n0 + lrow)) * RRK + (j & 15);
            }
            cp16(sB + (uint32_t)(buf * TILEB + lrow * 80 + c * 16), gq);
        }
    };

    // prologue: two stages in flight
    load_tiles(0, 0);
    asm volatile("cp.async.commit_group;");
    load_tiles(1, 1);
    asm volatile("cp.async.commit_group;");

    int s = 0;
    for (int kt = 0; kt < NK; ++kt) {
        asm volatile("cp.async.wait_group 1;");   // group kt complete
        __syncthreads();                          // all warps past compute(kt-1)

        // issue loads for kt+2 into stage (kt+2)%NS == (kt-1)%NS (freed by the sync)
        if (kt + 2 < NK) {
            int s2 = (kt + 2) % NS;
            load_tiles(kt + 2, s2);
        }
        asm volatile("cp.async.commit_group;");

        const uint32_t* As = (const uint32_t*)(smem + s * TILEB);
        const uint32_t* Bs = (const uint32_t*)(smem + NS * TILEB + s * TILEB);
        #pragma unroll
        for (int s2 = 0; s2 < 2; s2++) {               // two k16 slices
            uint32_t af[4][4], bf[4][2];
            int kw = s2 * 8 + tig;
            #pragma unroll
            for (int i = 0; i < 4; i++) {
                int m = wm * 64 + i * 16 + grp;
                af[i][0] = As[m * RS + kw];
                af[i][1] = As[(m + 8) * RS + kw];
                af[i][2] = As[m * RS + kw + 4];
                af[i][3] = As[(m + 8) * RS + kw + 4];
            }
            #pragma unroll
            for (int j = 0; j < 4; j++) {
                int n = wn * 32 + j * 8 + grp;
                bf[j][0] = Bs[n * RS + kw];
                bf[j][1] = Bs[n * RS + kw + 4];
            }
            #pragma unroll
            for (int i = 0; i < 4; i++)
                #pragma unroll
                for (int j = 0; j < 4; j++)
                    mma_f16(acc[i][j], af[i], bf[j]);
        }
        s = (s == NS - 1) ? 0 : s + 1;
    }

    // epilogue
    #pragma unroll
    for (int i = 0; i < 4; i++) {
        int t0 = m0 + wm * 64 + i * 16 + grp;
        int e0 = 0, e1 = 0;
        if (MASK) { e0 = eidx[t0]; e1 = eidx[t0 + 8]; }
        #pragma unroll
        for (int j = 0; j < 4; j++) {
            int n = n0 + wn * 32 + j * 8 + 2 * tig;
            if (MASK) {
                __half2* C = (__half2*)Cout;
                bool h0 = ((n >> 4) == e0), h1 = ((n >> 4) == e1);
                __half2 z = __floats2half2_rn(0.f, 0.f);
                C[((size_t)t0 * Nsz + n) >> 1] =
                    h0 ? __floats2half2_rn(SCAL * acc[i][j][0], SCAL * acc[i][j][1]) : z;
                C[((size_t)(t0 + 8) * Nsz + n) >> 1] =
                    h1 ? __floats2half2_rn(SCAL * acc[i][j][2], SCAL * acc[i][j][3]) : z;
            } else if (GELU) {
                __half2* C = (__half2*)Cout;
                float bv0 = bias[n], bv1 = bias[n + 1];
                C[((size_t)t0 * Nsz + n) >> 1] = __floats2half2_rn(
                    gelu_new_f(acc[i][j][0] + bv0), gelu_new_f(acc[i][j][1] + bv1));
                C[((size_t)(t0 + 8) * Nsz + n) >> 1] = __floats2half2_rn(
                    gelu_new_f(acc[i][j][2] + bv0), gelu_new_f(acc[i][j][3] + bv1));
            } else {
                float* C = (float*)Cout;
                float bv0 = bias[n], bv1 = bias[n + 1];
                float2 v0 = {acc[i][j][0] + bv0, acc[i][j][1] + bv1};
                float2 v1 = {acc[i][j][2] + bv0, acc[i][j][3] + bv1};
                *reinterpret_cast<float2*>(&C[(size_t)t0 * Nsz + n]) = v0;
                *reinterpret_cast<float2*>(&C[(size_t)(t0 + 8) * Nsz + n]) = v1;
            }
        }
    }
}

// ---------------- launch --------------------------------------------------------
extern "C" void kernel_launch(void* const* d_in, const int* in_sizes, int n_in,
                              void* d_out, int out_size) {
    const float* x  = (const float*)d_in[0];
    const int*   ei = (const int*)  d_in[1];
    const float* W1 = (const float*)d_in[2];
    const float* b1 = (const float*)d_in[3];
    const float* A1 = (const float*)d_in[4];
    const float* B1 = (const float*)d_in[5];
    const float* W2 = (const float*)d_in[6];
    const float* b2 = (const float*)d_in[7];
    const float* A2 = (const float*)d_in[8];
    const float* B2 = (const float*)d_in[9];
    float* out = (float*)d_out;

    __half *pW1, *pW2, *pB1, *pB2, *pA1, *pA2, *pX, *pY, *pZ1, *pZ2;
    cudaGetSymbolAddress((void**)&pW1, g_W1h);
    cudaGetSymbolAddress((void**)&pW2, g_W2h);
    cudaGetSymbolAddress((void**)&pB1, g_B1h);
    cudaGetSymbolAddress((void**)&pB2, g_B2h);
    cudaGetSymbolAddress((void**)&pA1, g_A1h);
    cudaGetSymbolAddress((void**)&pA2, g_A2h);
    cudaGetSymbolAddress((void**)&pX,  g_Xh);
    cudaGetSymbolAddress((void**)&pY,  g_Yh);
    cudaGetSymbolAddress((void**)&pZ1, g_Z1h);
    cudaGetSymbolAddress((void**)&pZ2, g_Z2h);

    cudaFuncSetAttribute(moe_gemm_h<DD, true,  true,  false>,
                         cudaFuncAttributeMaxDynamicSharedMemorySize, SMEMSZ);
    cudaFuncSetAttribute(moe_gemm_h<HH, true,  false, false>,
                         cudaFuncAttributeMaxDynamicSharedMemorySize, SMEMSZ);
    cudaFuncSetAttribute(moe_gemm_h<DD, false, false, true>,
                         cudaFuncAttributeMaxDynamicSharedMemorySize, SMEMSZ);
    cudaFuncSetAttribute(moe_gemm_h<HH, false, false, true>,
                         cudaFuncAttributeMaxDynamicSharedMemorySize, SMEMSZ);

    int n4;
    // layer-1 prep
    n4 = HH * DD / 4;        tohalf_k<<<(n4 + 255) / 256, 256>>>((__half2*)pW1, (const float4*)W1, n4);
    n4 = NE * HH * RRK / 4;  tohalf_k<<<(n4 + 255) / 256, 256>>>((__half2*)pB1, (const float4*)B1, n4);
    n4 = TT * DD / 4;        tohalf_k<<<(n4 + 255) / 256, 256>>>((__half2*)pX,  (const float4*)x,  n4);
    n4 = ER * DD / 4;        tohalf_k<<<(n4 + 255) / 256, 256>>>((__half2*)pA1, (const float4*)A1, n4);

    // Z1 = mask(SCAL * X @ A1^T)  -> half
    moe_gemm_h<DD, false, false, true><<<dim3(1, TT / BM), 256, SMEMSZ>>>(
        pX, nullptr, pA1, nullptr, nullptr, ei, pZ1, ER);

    // fc1: Y = half(gelu(X@W1^T + b1 + Z1@B1^T))
    moe_gemm_h<DD, true, true, false><<<dim3(HH / BN, TT / BM), 256, SMEMSZ>>>(
        pX, pZ1, pW1, pB1, b1, nullptr, pY, HH);

    // layer-2 prep
    n4 = DD * HH / 4;        tohalf_k<<<(n4 + 255) / 256, 256>>>((__half2*)pW2, (const float4*)W2, n4);
    n4 = NE * DD * RRK / 4;  tohalf_k<<<(n4 + 255) / 256, 256>>>((__half2*)pB2, (const float4*)B2, n4);
    n4 = ER * HH / 4;        tohalf_k<<<(n4 + 255) / 256, 256>>>((__half2*)pA2, (const float4*)A2, n4);

    // Z2 = mask(SCAL * Y @ A2^T) -> half
    moe_gemm_h<HH, false, false, true><<<dim3(1, TT / BM), 256, SMEMSZ>>>(
        pY, nullptr, pA2, nullptr, nullptr, ei, pZ2, ER);

    // fc2: out = Y@W2^T + b2 + Z2@B2^T  (fp32 out)
    moe_gemm_h<HH, true, false, false><<<dim3(DD / BN, TT / BM), 256, SMEMSZ>>>(
        pY, pZ2, pW2, pB2, b2, nullptr, out, DD);
}

// round 10
// speedup vs baseline: 3.1974x; 1.3677x over previous
#include <cuda_runtime.h>
#include <cuda_fp16.h>
#include <cstdint>

#define TT 4096
#define DD 2048
#define HH 8192
#define NE 8
#define RRK 16
#define ER 128
#define SCAL 2.0f

#define BM 128
#define BN 128
#define BK 64                  // 64 halfs of K per tile
#define NS 3
#define RS 36                  // smem row stride in 32-bit words (72 halfs) — conflict-free
#define TILEB (BM * RS * 4)    // 18432 B per operand tile
#define SMEMSZ (NS * 2 * TILEB) // 110592 B -> 2 CTAs/SM (221 KB of 228)

// ---------------- scratch (device globals) ------------------------------------
__device__ __half g_W1h[(size_t)HH * DD];
__device__ __half g_W2h[(size_t)DD * HH];
__device__ __half g_B1h[(size_t)NE * HH * RRK];
__device__ __half g_B2h[(size_t)NE * DD * RRK];
__device__ __half g_A1h[(size_t)ER * DD];
__device__ __half g_A2h[(size_t)ER * HH];
__device__ __half g_Xh [(size_t)TT * DD];
__device__ __half g_Yh [(size_t)TT * HH];
__device__ __half g_Z1h[TT * ER];
__device__ __half g_Z2h[TT * ER];

// ---------------- helpers ------------------------------------------------------
__device__ __forceinline__ void cp16(uint32_t s, const void* g) {
    asm volatile("cp.async.cg.shared.global [%0], [%1], 16;" :: "r"(s), "l"(g));
}
__device__ __forceinline__ float gelu_new_f(float x) {
    float x3 = x * x * x;
    float inner = 0.7978845608028654f * (x + 0.044715f * x3);
    return 0.5f * x * (1.0f + tanhf(inner));
}
__device__ __forceinline__ void mma_f16(float* c, const uint32_t* a, const uint32_t* b) {
    asm volatile(
        "mma.sync.aligned.m16n8k16.row.col.f32.f16.f16.f32 "
        "{%0,%1,%2,%3}, {%4,%5,%6,%7}, {%8,%9}, {%0,%1,%2,%3};"
        : "+f"(c[0]), "+f"(c[1]), "+f"(c[2]), "+f"(c[3])
        : "r"(a[0]), "r"(a[1]), "r"(a[2]), "r"(a[3]), "r"(b[0]), "r"(b[1]));
}

// ---------------- fp32 -> fp16 convert ----------------------------------------
__global__ void tohalf_k(__half2* __restrict__ dst, const float4* __restrict__ src, int n4) {
    int i = blockIdx.x * blockDim.x + threadIdx.x;
    if (i < n4) {
        float4 v = src[i];
        dst[2 * i + 0] = __floats2half2_rn(v.x, v.y);
        dst[2 * i + 1] = __floats2half2_rn(v.z, v.w);
    }
}

// ---------------- fp16 GEMM: C[T,N] = [A0|AL] @ [W|BL]^T -----------------------
// 3-stage cp.async ring, single __syncthreads per ktile, BK=64.
template<int K0, bool TAIL, bool GELU, bool MASK>
__global__ void __launch_bounds__(256, 2)
moe_gemm_h(const __half* __restrict__ A0, const __half* __restrict__ AL,
           const __half* __restrict__ W,  const __half* __restrict__ BL,
           const float* __restrict__ bias, const int* __restrict__ eidx,
           void* __restrict__ Cout, int Nsz) {
    extern __shared__ __align__(128) char smem[];
    const int NK = (K0 + (TAIL ? ER : 0)) / BK;
    const int m0 = blockIdx.y * BM, n0 = blockIdx.x * BN;
    const int tid  = threadIdx.x;
    const int warp = tid >> 5, wm = warp >> 2, wn = warp & 3;   // 2x4 warps, 64x32
    const int lane = tid & 31, grp = lane >> 2, tig = lane & 3;
    const int lr = tid >> 3, lc = tid & 7;                       // loader: 32 rows x 8 chunks

    float acc[4][4][4];
    #pragma unroll
    for (int i = 0; i < 4; i++)
        #pragma unroll
        for (int j = 0; j < 4; j++)
            #pragma unroll
            for (int c = 0; c < 4; c++) acc[i][j][c] = 0.f;

    const uint32_t sA = (uint32_t)__cvta_generic_to_shared(smem);
    const uint32_t sB = sA + NS * TILEB;

    auto load_tiles = [&](int kt, int buf) {
        int kk = kt * BK + lc * 8;                 // K0 % 64 == 0: chunk never straddles
        #pragma unroll
        for (int p = 0; p < 4; p++) {
            int row = lr + p * 32;
            const __half* gp = (!TAIL || kk < K0)
                ? A0 + (size_t)(m0 + row) * K0 + kk
                : AL + (size_t)(m0 + row) * ER + (kk - K0);
            cp16(sA + (uint32_t)(buf * TILEB + row * 144 + lc * 16), gp);
            const __half* gq;
            if (!TAIL || kk < K0) {
                gq = W + (size_t)(n0 + row) * K0 + kk;
            } else {
                int j = kk - K0;                   // e = j>>4, r = j&15 (0 or 8)
                gq = BL + ((size_t)(j >> 4) * Nsz + (n0 + row)) * RRK + (j & 15);
            }
            cp16(sB + (uint32_t)(buf * TILEB + row * 144 + lc * 16), gq);
        }
    };

    // prologue: two stages in flight
    load_tiles(0, 0);
    asm volatile("cp.async.commit_group;");
    load_tiles(1, 1);
    asm volatile("cp.async.commit_group;");

    int s = 0;
    for (int kt = 0; kt < NK; ++kt) {
        asm volatile("cp.async.wait_group 1;");   // group kt complete
        __syncthreads();                          // all warps past compute(kt-1)

        if (kt + 2 < NK) load_tiles(kt + 2, (kt + 2) % NS);
        asm volatile("cp.async.commit_group;");

        const uint32_t* As = (const uint32_t*)(smem + s * TILEB);
        const uint32_t* Bs = (const uint32_t*)(smem + NS * TILEB + s * TILEB);
        #pragma unroll
        for (int s2 = 0; s2 < 4; s2++) {               // four k16 slices
            uint32_t af[4][4], bf[4][2];
            int kw = s2 * 8 + tig;
            #pragma unroll
            for (int i = 0; i < 4; i++) {
                int m = wm * 64 + i * 16 + grp;
                af[i][0] = As[m * RS + kw];
                af[i][1] = As[(m + 8) * RS + kw];
                af[i][2] = As[m * RS + kw + 4];
                af[i][3] = As[(m + 8) * RS + kw + 4];
            }
            #pragma unroll
            for (int j = 0; j < 4; j++) {
                int n = wn * 32 + j * 8 + grp;
                bf[j][0] = Bs[n * RS + kw];
                bf[j][1] = Bs[n * RS + kw + 4];
            }
            #pragma unroll
            for (int i = 0; i < 4; i++)
                #pragma unroll
                for (int j = 0; j < 4; j++)
                    mma_f16(acc[i][j], af[i], bf[j]);
        }
        s = (s == NS - 1) ? 0 : s + 1;
    }

    // epilogue
    #pragma unroll
    for (int i = 0; i < 4; i++) {
        int t0 = m0 + wm * 64 + i * 16 + grp;
        int e0 = 0, e1 = 0;
        if (MASK) { e0 = eidx[t0]; e1 = eidx[t0 + 8]; }
        #pragma unroll
        for (int j = 0; j < 4; j++) {
            int n = n0 + wn * 32 + j * 8 + 2 * tig;
            if (MASK) {
                __half2* C = (__half2*)Cout;
                bool h0 = ((n >> 4) == e0), h1 = ((n >> 4) == e1);
                __half2 z = __floats2half2_rn(0.f, 0.f);
                C[((size_t)t0 * Nsz + n) >> 1] =
                    h0 ? __floats2half2_rn(SCAL * acc[i][j][0], SCAL * acc[i][j][1]) : z;
                C[((size_t)(t0 + 8) * Nsz + n) >> 1] =
                    h1 ? __floats2half2_rn(SCAL * acc[i][j][2], SCAL * acc[i][j][3]) : z;
            } else if (GELU) {
                __half2* C = (__half2*)Cout;
                float bv0 = bias[n], bv1 = bias[n + 1];
                C[((size_t)t0 * Nsz + n) >> 1] = __floats2half2_rn(
                    gelu_new_f(acc[i][j][0] + bv0), gelu_new_f(acc[i][j][1] + bv1));
                C[((size_t)(t0 + 8) * Nsz + n) >> 1] = __floats2half2_rn(
                    gelu_new_f(acc[i][j][2] + bv0), gelu_new_f(acc[i][j][3] + bv1));
            } else {
                float* C = (float*)Cout;
                float bv0 = bias[n], bv1 = bias[n + 1];
                float2 v0 = {acc[i][j][0] + bv0, acc[i][j][1] + bv1};
                float2 v1 = {acc[i][j][2] + bv0, acc[i][j][3] + bv1};
                *reinterpret_cast<float2*>(&C[(size_t)t0 * Nsz + n]) = v0;
                *reinterpret_cast<float2*>(&C[(size_t)(t0 + 8) * Nsz + n]) = v1;
            }
        }
    }
}

// ---------------- launch --------------------------------------------------------
extern "C" void kernel_launch(void* const* d_in, const int* in_sizes, int n_in,
                              void* d_out, int out_size) {
    const float* x  = (const float*)d_in[0];
    const int*   ei = (const int*)  d_in[1];
    const float* W1 = (const float*)d_in[2];
    const float* b1 = (const float*)d_in[3];
    const float* A1 = (const float*)d_in[4];
    const float* B1 = (const float*)d_in[5];
    const float* W2 = (const float*)d_in[6];
    const float* b2 = (const float*)d_in[7];
    const float* A2 = (const float*)d_in[8];
    const float* B2 = (const float*)d_in[9];
    float* out = (float*)d_out;

    __half *pW1, *pW2, *pB1, *pB2, *pA1, *pA2, *pX, *pY, *pZ1, *pZ2;
    cudaGetSymbolAddress((void**)&pW1, g_W1h);
    cudaGetSymbolAddress((void**)&pW2, g_W2h);
    cudaGetSymbolAddress((void**)&pB1, g_B1h);
    cudaGetSymbolAddress((void**)&pB2, g_B2h);
    cudaGetSymbolAddress((void**)&pA1, g_A1h);
    cudaGetSymbolAddress((void**)&pA2, g_A2h);
    cudaGetSymbolAddress((void**)&pX,  g_Xh);
    cudaGetSymbolAddress((void**)&pY,  g_Yh);
    cudaGetSymbolAddress((void**)&pZ1, g_Z1h);
    cudaGetSymbolAddress((void**)&pZ2, g_Z2h);

    cudaFuncSetAttribute(moe_gemm_h<DD, true,  true,  false>,
                         cudaFuncAttributeMaxDynamicSharedMemorySize, SMEMSZ);
    cudaFuncSetAttribute(moe_gemm_h<HH, true,  false, false>,
                         cudaFuncAttributeMaxDynamicSharedMemorySize, SMEMSZ);
    cudaFuncSetAttribute(moe_gemm_h<DD, false, false, true>,
                         cudaFuncAttributeMaxDynamicSharedMemorySize, SMEMSZ);
    cudaFuncSetAttribute(moe_gemm_h<HH, false, false, true>,
                         cudaFuncAttributeMaxDynamicSharedMemorySize, SMEMSZ);

    int n4;
    // layer-1 prep
    n4 = HH * DD / 4;        tohalf_k<<<(n4 + 255) / 256, 256>>>((__half2*)pW1, (const float4*)W1, n4);
    n4 = NE * HH * RRK / 4;  tohalf_k<<<(n4 + 255) / 256, 256>>>((__half2*)pB1, (const float4*)B1, n4);
    n4 = TT * DD / 4;        tohalf_k<<<(n4 + 255) / 256, 256>>>((__half2*)pX,  (const float4*)x,  n4);
    n4 = ER * DD / 4;        tohalf_k<<<(n4 + 255) / 256, 256>>>((__half2*)pA1, (const float4*)A1, n4);

    // Z1 = mask(SCAL * X @ A1^T)  -> half
    moe_gemm_h<DD, false, false, true><<<dim3(1, TT / BM), 256, SMEMSZ>>>(
        pX, nullptr, pA1, nullptr, nullptr, ei, pZ1, ER);

    // fc1: Y = half(gelu(X@W1^T + b1 + Z1@B1^T))
    moe_gemm_h<DD, true, true, false><<<dim3(HH / BN, TT / BM), 256, SMEMSZ>>>(
        pX, pZ1, pW1, pB1, b1, nullptr, pY, HH);

    // layer-2 prep
    n4 = DD * HH / 4;        tohalf_k<<<(n4 + 255) / 256, 256>>>((__half2*)pW2, (const float4*)W2, n4);
    n4 = NE * DD * RRK / 4;  tohalf_k<<<(n4 + 255) / 256, 256>>>((__half2*)pB2, (const float4*)B2, n4);
    n4 = ER * HH / 4;        tohalf_k<<<(n4 + 255) / 256, 256>>>((__half2*)pA2, (const float4*)A2, n4);

    // Z2 = mask(SCAL * Y @ A2^T) -> half
    moe_gemm_h<HH, false, false, true><<<dim3(1, TT / BM), 256, SMEMSZ>>>(
        pY, nullptr, pA2, nullptr, nullptr, ei, pZ2, ER);

    // fc2: out = Y@W2^T + b2 + Z2@B2^T  (fp32 out)
    moe_gemm_h<HH, true, false, false><<<dim3(DD / BN, TT / BM), 256, SMEMSZ>>>(
        pY, pZ2, pW2, pB2, b2, nullptr, out, DD);
}

// round 11
// speedup vs baseline: 3.5682x; 1.1160x over previous
#include <cuda_runtime.h>
#include <cuda_fp16.h>
#include <cstdint>

#define TT 4096
#define DD 2048
#define HH 8192
#define NE 8
#define RRK 16
#define ER 128
#define SCAL 2.0f

#define BM 128
#define BN 128
#define BK 64                  // 64 halfs of K per tile
#define NS 3
#define RS 36                  // smem row stride in 32-bit words (72 halfs) — conflict-free
#define TILEB (BM * RS * 4)    // 18432 B per operand tile
#define SMEMSZ (NS * 2 * TILEB) // 110592 B -> 2 CTAs/SM

#define SPLIT1 4
#define SPLIT2 8

// ---------------- scratch (device globals) ------------------------------------
__device__ __half g_W1h[(size_t)HH * DD];
__device__ __half g_W2h[(size_t)DD * HH];
__device__ __half g_B1h[(size_t)NE * HH * RRK];
__device__ __half g_B2h[(size_t)NE * DD * RRK];
__device__ __half g_A1h[(size_t)ER * DD];
__device__ __half g_A2h[(size_t)ER * HH];
__device__ __half g_Xh [(size_t)TT * DD];
__device__ __half g_Yh [(size_t)TT * HH];
__device__ __half g_Z1h[TT * ER];
__device__ __half g_Z2h[TT * ER];
__device__ float  g_Zp [(size_t)SPLIT2 * TT * ER];   // split-K partials (fp32)

// ---------------- helpers ------------------------------------------------------
__device__ __forceinline__ void cp16(uint32_t s, const void* g) {
    asm volatile("cp.async.cg.shared.global [%0], [%1], 16;" :: "r"(s), "l"(g));
}
__device__ __forceinline__ float gelu_new_f(float x) {
    float x3 = x * x * x;
    float inner = 0.7978845608028654f * (x + 0.044715f * x3);
    return 0.5f * x * (1.0f + tanhf(inner));
}
__device__ __forceinline__ void mma_f16(float* c, const uint32_t* a, const uint32_t* b) {
    asm volatile(
        "mma.sync.aligned.m16n8k16.row.col.f32.f16.f16.f32 "
        "{%0,%1,%2,%3}, {%4,%5,%6,%7}, {%8,%9}, {%0,%1,%2,%3};"
        : "+f"(c[0]), "+f"(c[1]), "+f"(c[2]), "+f"(c[3])
        : "r"(a[0]), "r"(a[1]), "r"(a[2]), "r"(a[3]), "r"(b[0]), "r"(b[1]));
}

// ---------------- merged fp32 -> fp16 conversion (all 7 tensors) ---------------
struct ConvSeg { const float4* src; __half2* dst; int n4; };

__global__ void tohalf_all_k(ConvSeg s0, ConvSeg s1, ConvSeg s2, ConvSeg s3,
                             ConvSeg s4, ConvSeg s5, ConvSeg s6, int total4) {
    ConvSeg segs[7] = {s0, s1, s2, s3, s4, s5, s6};
    for (int i = blockIdx.x * blockDim.x + threadIdx.x; i < total4;
         i += gridDim.x * blockDim.x) {
        int r = i;
        #pragma unroll
        for (int k = 0; k < 7; k++) {
            if (r < segs[k].n4) {
                float4 v = segs[k].src[r];
                segs[k].dst[2 * r + 0] = __floats2half2_rn(v.x, v.y);
                segs[k].dst[2 * r + 1] = __floats2half2_rn(v.z, v.w);
                break;
            }
            r -= segs[k].n4;
        }
    }
}

// ---------------- Z reduce: sum split-K partials, mask, scale, -> half ---------
template<int SPLIT>
__global__ void zreduce_k(const float* __restrict__ Zp, const int* __restrict__ eidx,
                          __half* __restrict__ Z) {
    int idx = blockIdx.x * blockDim.x + threadIdx.x;   // t*ER + j
    int t = idx >> 7, j = idx & 127;
    float v = 0.f;
    if ((j >> 4) == eidx[t]) {
        #pragma unroll
        for (int s = 0; s < SPLIT; s++) v += Zp[(size_t)s * TT * ER + idx];
        v *= SCAL;
    }
    Z[idx] = __float2half_rn(v);
}

// ---------------- fp16 GEMM: C[T,N] = [A0|AL] @ [W|BL]^T -----------------------
// 3-stage cp.async ring, single __syncthreads per ktile, BK=64.
// PART: split-K partial (blockIdx.z selects K chunk), fp32 out, no bias/mask.
template<int K0, bool TAIL, bool GELU, bool PART>
__global__ void __launch_bounds__(256, 2)
moe_gemm_h(const __half* __restrict__ A0, const __half* __restrict__ AL,
           const __half* __restrict__ W,  const __half* __restrict__ BL,
           const float* __restrict__ bias, void* __restrict__ Cout,
           int Nsz, int nkt, int kch) {
    extern __shared__ __align__(128) char smem[];
    const int NK = nkt;
    const int kbase = PART ? blockIdx.z * kch : 0;
    const int m0 = blockIdx.y * BM, n0 = blockIdx.x * BN;
    const int tid  = threadIdx.x;
    const int warp = tid >> 5, wm = warp >> 2, wn = warp & 3;   // 2x4 warps, 64x32
    const int lane = tid & 31, grp = lane >> 2, tig = lane & 3;
    const int lr = tid >> 3, lc = tid & 7;                       // loader: 32 rows x 8 chunks

    float acc[4][4][4];
    #pragma unroll
    for (int i = 0; i < 4; i++)
        #pragma unroll
        for (int j = 0; j < 4; j++)
            #pragma unroll
            for (int c = 0; c < 4; c++) acc[i][j][c] = 0.f;

    const uint32_t sA = (uint32_t)__cvta_generic_to_shared(smem);
    const uint32_t sB = sA + NS * TILEB;

    auto load_tiles = [&](int kt, int buf) {
        int kk = kbase + kt * BK + lc * 8;
        #pragma unroll
        for (int p = 0; p < 4; p++) {
            int row = lr + p * 32;
            const __half* gp = (!TAIL || kk < K0)
                ? A0 + (size_t)(m0 + row) * K0 + kk
                : AL + (size_t)(m0 + row) * ER + (kk - K0);
            cp16(sA + (uint32_t)(buf * TILEB + row * 144 + lc * 16), gp);
            const __half* gq;
            if (!TAIL || kk < K0) {
                gq = W + (size_t)(n0 + row) * K0 + kk;
            } else {
                int j = kk - K0;                   // e = j>>4, r = j&15
                gq = BL + ((size_t)(j >> 4) * Nsz + (n0 + row)) * RRK + (j & 15);
            }
            cp16(sB + (uint32_t)(buf * TILEB + row * 144 + lc * 16), gq);
        }
    };

    load_tiles(0, 0);
    asm volatile("cp.async.commit_group;");
    load_tiles(1, 1);
    asm volatile("cp.async.commit_group;");

    int s = 0;
    for (int kt = 0; kt < NK; ++kt) {
        asm volatile("cp.async.wait_group 1;");
        __syncthreads();

        if (kt + 2 < NK) load_tiles(kt + 2, (kt + 2) % NS);
        asm volatile("cp.async.commit_group;");

        const uint32_t* As = (const uint32_t*)(smem + s * TILEB);
        const uint32_t* Bs = (const uint32_t*)(smem + NS * TILEB + s * TILEB);
        #pragma unroll
        for (int s2 = 0; s2 < 4; s2++) {               // four k16 slices
            uint32_t af[4][4], bf[4][2];
            int kw = s2 * 8 + tig;
            #pragma unroll
            for (int i = 0; i < 4; i++) {
                int m = wm * 64 + i * 16 + grp;
                af[i][0] = As[m * RS + kw];
                af[i][1] = As[(m + 8) * RS + kw];
                af[i][2] = As[m * RS + kw + 4];
                af[i][3] = As[(m + 8) * RS + kw + 4];
            }
            #pragma unroll
            for (int j = 0; j < 4; j++) {
                int n = wn * 32 + j * 8 + grp;
                bf[j][0] = Bs[n * RS + kw];
                bf[j][1] = Bs[n * RS + kw + 4];
            }
            #pragma unroll
            for (int i = 0; i < 4; i++)
                #pragma unroll
                for (int j = 0; j < 4; j++)
                    mma_f16(acc[i][j], af[i], bf[j]);
        }
        s = (s == NS - 1) ? 0 : s + 1;
    }

    // epilogue
    #pragma unroll
    for (int i = 0; i < 4; i++) {
        int t0 = m0 + wm * 64 + i * 16 + grp;
        #pragma unroll
        for (int j = 0; j < 4; j++) {
            int n = n0 + wn * 32 + j * 8 + 2 * tig;
            if (PART) {
                float* C = (float*)Cout + (size_t)blockIdx.z * TT * ER;
                float2 v0 = {acc[i][j][0], acc[i][j][1]};
                float2 v1 = {acc[i][j][2], acc[i][j][3]};
                *reinterpret_cast<float2*>(&C[(size_t)t0 * Nsz + n]) = v0;
                *reinterpret_cast<float2*>(&C[(size_t)(t0 + 8) * Nsz + n]) = v1;
            } else if (GELU) {
                __half2* C = (__half2*)Cout;
                float bv0 = bias[n], bv1 = bias[n + 1];
                C[((size_t)t0 * Nsz + n) >> 1] = __floats2half2_rn(
                    gelu_new_f(acc[i][j][0] + bv0), gelu_new_f(acc[i][j][1] + bv1));
                C[((size_t)(t0 + 8) * Nsz + n) >> 1] = __floats2half2_rn(
                    gelu_new_f(acc[i][j][2] + bv0), gelu_new_f(acc[i][j][3] + bv1));
            } else {
                float* C = (float*)Cout;
                float bv0 = bias[n], bv1 = bias[n + 1];
                float2 v0 = {acc[i][j][0] + bv0, acc[i][j][1] + bv1};
                float2 v1 = {acc[i][j][2] + bv0, acc[i][j][3] + bv1};
                *reinterpret_cast<float2*>(&C[(size_t)t0 * Nsz + n]) = v0;
                *reinterpret_cast<float2*>(&C[(size_t)(t0 + 8) * Nsz + n]) = v1;
            }
        }
    }
}

// ---------------- launch --------------------------------------------------------
extern "C" void kernel_launch(void* const* d_in, const int* in_sizes, int n_in,
                              void* d_out, int out_size) {
    const float* x  = (const float*)d_in[0];
    const int*   ei = (const int*)  d_in[1];
    const float* W1 = (const float*)d_in[2];
    const float* b1 = (const float*)d_in[3];
    const float* A1 = (const float*)d_in[4];
    const float* B1 = (const float*)d_in[5];
    const float* W2 = (const float*)d_in[6];
    const float* b2 = (const float*)d_in[7];
    const float* A2 = (const float*)d_in[8];
    const float* B2 = (const float*)d_in[9];
    float* out = (float*)d_out;

    __half *pW1, *pW2, *pB1, *pB2, *pA1, *pA2, *pX, *pY, *pZ1, *pZ2;
    float* pZp;
    cudaGetSymbolAddress((void**)&pW1, g_W1h);
    cudaGetSymbolAddress((void**)&pW2, g_W2h);
    cudaGetSymbolAddress((void**)&pB1, g_B1h);
    cudaGetSymbolAddress((void**)&pB2, g_B2h);
    cudaGetSymbolAddress((void**)&pA1, g_A1h);
    cudaGetSymbolAddress((void**)&pA2, g_A2h);
    cudaGetSymbolAddress((void**)&pX,  g_Xh);
    cudaGetSymbolAddress((void**)&pY,  g_Yh);
    cudaGetSymbolAddress((void**)&pZ1, g_Z1h);
    cudaGetSymbolAddress((void**)&pZ2, g_Z2h);
    cudaGetSymbolAddress((void**)&pZp, g_Zp);

    cudaFuncSetAttribute(moe_gemm_h<DD, true,  true,  false>,
                         cudaFuncAttributeMaxDynamicSharedMemorySize, SMEMSZ);
    cudaFuncSetAttribute(moe_gemm_h<HH, true,  false, false>,
                         cudaFuncAttributeMaxDynamicSharedMemorySize, SMEMSZ);
    cudaFuncSetAttribute(moe_gemm_h<DD, false, false, true>,
                         cudaFuncAttributeMaxDynamicSharedMemorySize, SMEMSZ);
    cudaFuncSetAttribute(moe_gemm_h<HH, false, false, true>,
                         cudaFuncAttributeMaxDynamicSharedMemorySize, SMEMSZ);

    // one merged conversion for all 7 tensors
    ConvSeg s0 = {(const float4*)W1, (__half2*)pW1, HH * DD / 4};
    ConvSeg s1 = {(const float4*)W2, (__half2*)pW2, DD * HH / 4};
    ConvSeg s2 = {(const float4*)x,  (__half2*)pX,  TT * DD / 4};
    ConvSeg s3 = {(const float4*)B1, (__half2*)pB1, NE * HH * RRK / 4};
    ConvSeg s4 = {(const float4*)B2, (__half2*)pB2, NE * DD * RRK / 4};
    ConvSeg s5 = {(const float4*)A1, (__half2*)pA1, ER * DD / 4};
    ConvSeg s6 = {(const float4*)A2, (__half2*)pA2, ER * HH / 4};
    int total4 = s0.n4 + s1.n4 + s2.n4 + s3.n4 + s4.n4 + s5.n4 + s6.n4;
    tohalf_all_k<<<2048, 256>>>(s0, s1, s2, s3, s4, s5, s6, total4);

    // Z1 partials: split-K over K=2048 (4 chunks of 512)
    moe_gemm_h<DD, false, false, true><<<dim3(1, TT / BM, SPLIT1), 256, SMEMSZ>>>(
        pX, nullptr, pA1, nullptr, nullptr, pZp, ER, (DD / SPLIT1) / BK, DD / SPLIT1);
    zreduce_k<SPLIT1><<<TT * ER / 256, 256>>>(pZp, ei, pZ1);

    // fc1: Y = half(gelu(X@W1^T + b1 + Z1@B1^T))
    moe_gemm_h<DD, true, true, false><<<dim3(HH / BN, TT / BM), 256, SMEMSZ>>>(
        pX, pZ1, pW1, pB1, b1, pY, HH, (DD + ER) / BK, 0);

    // Z2 partials: split-K over K=8192 (8 chunks of 1024)
    moe_gemm_h<HH, false, false, true><<<dim3(1, TT / BM, SPLIT2), 256, SMEMSZ>>>(
        pY, nullptr, pA2, nullptr, nullptr, pZp, ER, (HH / SPLIT2) / BK, HH / SPLIT2);
    zreduce_k<SPLIT2><<<TT * ER / 256, 256>>>(pZp, ei, pZ2);

    // fc2: out = Y@W2^T + b2 + Z2@B2^T  (fp32 out)
    moe_gemm_h<HH, true, false, false><<<dim3(DD / BN, TT / BM), 256, SMEMSZ>>>(
        pY, pZ2, pW2, pB2, b2, out, DD, (HH + ER) / BK, 0);
}

// round 12
// speedup vs baseline: 3.9604x; 1.1099x over previous
#include <cuda_runtime.h>
#include <cuda_fp16.h>
#include <cstdint>

#define TT 4096
#define DD 2048
#define HH 8192
#define NE 8
#define RRK 16
#define ER 128
#define SCAL 2.0f

#define BM 128
#define BN 128
#define BK 64                  // 64 halfs of K per tile
#define NS 3
#define RS 36                  // smem row stride in words (144 B) — LDS & ldmatrix conflict-free
#define ROWB 144
#define TILEB (BM * RS * 4)    // 18432 B per operand tile
#define SMEMSZ (NS * 2 * TILEB) // 110592 B -> 2 CTAs/SM

#define SPLIT1 4
#define SPLIT2 8

// ---------------- scratch (device globals) ------------------------------------
__device__ __half g_W1h[(size_t)HH * DD];
__device__ __half g_W2h[(size_t)DD * HH];
__device__ __half g_B1h[(size_t)NE * HH * RRK];
__device__ __half g_B2h[(size_t)NE * DD * RRK];
__device__ __half g_A1h[(size_t)ER * DD];
__device__ __half g_A2h[(size_t)ER * HH];
__device__ __half g_Xh [(size_t)TT * DD];
__device__ __half g_Yh [(size_t)TT * HH];
__device__ __half g_Z1h[TT * ER];
__device__ __half g_Z2h[TT * ER];
__device__ float  g_Zp [(size_t)SPLIT2 * TT * ER];   // split-K partials (fp32)

// ---------------- helpers ------------------------------------------------------
__device__ __forceinline__ void cp16(uint32_t s, const void* g) {
    asm volatile("cp.async.cg.shared.global [%0], [%1], 16;" :: "r"(s), "l"(g));
}
__device__ __forceinline__ float gelu_new_f(float x) {
    float x3 = x * x * x;
    float inner = 0.7978845608028654f * (x + 0.044715f * x3);
    return 0.5f * x * (1.0f + tanhf(inner));
}
__device__ __forceinline__ void mma_f16(float* c, const uint32_t* a, const uint32_t* b) {
    asm volatile(
        "mma.sync.aligned.m16n8k16.row.col.f32.f16.f16.f32 "
        "{%0,%1,%2,%3}, {%4,%5,%6,%7}, {%8,%9}, {%0,%1,%2,%3};"
        : "+f"(c[0]), "+f"(c[1]), "+f"(c[2]), "+f"(c[3])
        : "r"(a[0]), "r"(a[1]), "r"(a[2]), "r"(a[3]), "r"(b[0]), "r"(b[1]));
}
#define LDSM4(d, a) \
    asm volatile("ldmatrix.sync.aligned.m8n8.x4.shared.b16 {%0,%1,%2,%3}, [%4];" \
        : "=r"((d)[0]), "=r"((d)[1]), "=r"((d)[2]), "=r"((d)[3]) : "r"(a))

// ---------------- merged fp32 -> fp16 conversion (all 7 tensors) ---------------
struct ConvSeg { const float4* src; __half2* dst; int n4; };

__global__ void tohalf_all_k(ConvSeg s0, ConvSeg s1, ConvSeg s2, ConvSeg s3,
                             ConvSeg s4, ConvSeg s5, ConvSeg s6, int total4) {
    ConvSeg segs[7] = {s0, s1, s2, s3, s4, s5, s6};
    for (int i = blockIdx.x * blockDim.x + threadIdx.x; i < total4;
         i += gridDim.x * blockDim.x) {
        int r = i;
        #pragma unroll
        for (int k = 0; k < 7; k++) {
            if (r < segs[k].n4) {
                float4 v = segs[k].src[r];
                segs[k].dst[2 * r + 0] = __floats2half2_rn(v.x, v.y);
                segs[k].dst[2 * r + 1] = __floats2half2_rn(v.z, v.w);
                break;
            }
            r -= segs[k].n4;
        }
    }
}

// ---------------- Z reduce: sum split-K partials, mask, scale, -> half ---------
template<int SPLIT>
__global__ void zreduce_k(const float* __restrict__ Zp, const int* __restrict__ eidx,
                          __half* __restrict__ Z) {
    int idx = blockIdx.x * blockDim.x + threadIdx.x;   // t*ER + j
    int t = idx >> 7, j = idx & 127;
    float v = 0.f;
    if ((j >> 4) == eidx[t]) {
        #pragma unroll
        for (int s = 0; s < SPLIT; s++) v += Zp[(size_t)s * TT * ER + idx];
        v *= SCAL;
    }
    Z[idx] = __float2half_rn(v);
}

// ---------------- fp16 GEMM: C[T,N] = [A0|AL] @ [W|BL]^T -----------------------
// 3-stage cp.async ring, one __syncthreads per ktile, BK=64, ldmatrix fragments.
template<int K0, bool TAIL, bool GELU, bool PART>
__global__ void __launch_bounds__(256, 2)
moe_gemm_h(const __half* __restrict__ A0, const __half* __restrict__ AL,
           const __half* __restrict__ W,  const __half* __restrict__ BL,
           const float* __restrict__ bias, void* __restrict__ Cout,
           int Nsz, int nkt, int kch) {
    extern __shared__ __align__(128) char smem[];
    const int NK = nkt;
    const int kbase = PART ? blockIdx.z * kch : 0;
    const int m0 = blockIdx.y * BM, n0 = blockIdx.x * BN;
    const int tid  = threadIdx.x;
    const int warp = tid >> 5, wm = warp >> 2, wn = warp & 3;   // 2x4 warps, 64x32
    const int lane = tid & 31, grp = lane >> 2, tig = lane & 3;
    const int lr = tid >> 3, lc = tid & 7;                       // loader: 32 rows x 8 chunks

    float acc[4][4][4];
    #pragma unroll
    for (int i = 0; i < 4; i++)
        #pragma unroll
        for (int j = 0; j < 4; j++)
            #pragma unroll
            for (int c = 0; c < 4; c++) acc[i][j][c] = 0.f;

    const uint32_t sA = (uint32_t)__cvta_generic_to_shared(smem);
    const uint32_t sB = sA + NS * TILEB;

    // ldmatrix per-lane base addresses (stage 0)
    const int l7 = lane & 7, lb = (lane >> 3) & 1, lh = lane >> 4;
    // A: matrices [m..m+7 | m+8..m+15] x [k | k+8]
    const uint32_t lmA = sA + (uint32_t)((wm * 64 + l7 + lb * 8) * ROWB + lh * 16);
    // B: matrices [n..n+7 k | n..n+7 k+8 | n+8..n+15 k | n+8..n+15 k+8]
    const uint32_t lmB = sB + (uint32_t)((wn * 32 + l7 + lh * 8) * ROWB + lb * 16);

    auto load_tiles = [&](int kt, int buf) {
        int kk = kbase + kt * BK + lc * 8;
        #pragma unroll
        for (int p = 0; p < 4; p++) {
            int row = lr + p * 32;
            const __half* gp = (!TAIL || kk < K0)
                ? A0 + (size_t)(m0 + row) * K0 + kk
                : AL + (size_t)(m0 + row) * ER + (kk - K0);
            cp16(sA + (uint32_t)(buf * TILEB + row * ROWB + lc * 16), gp);
            const __half* gq;
            if (!TAIL || kk < K0) {
                gq = W + (size_t)(n0 + row) * K0 + kk;
            } else {
                int j = kk - K0;                   // e = j>>4, r = j&15
                gq = BL + ((size_t)(j >> 4) * Nsz + (n0 + row)) * RRK + (j & 15);
            }
            cp16(sB + (uint32_t)(buf * TILEB + row * ROWB + lc * 16), gq);
        }
    };

    load_tiles(0, 0);
    asm volatile("cp.async.commit_group;");
    load_tiles(1, 1);
    asm volatile("cp.async.commit_group;");

    int s = 0;
    for (int kt = 0; kt < NK; ++kt) {
        asm volatile("cp.async.wait_group 1;");
        __syncthreads();

        if (kt + 2 < NK) load_tiles(kt + 2, (kt + 2) % NS);
        asm volatile("cp.async.commit_group;");

        const uint32_t stA = lmA + s * TILEB;
        const uint32_t stB = lmB + s * TILEB;
        #pragma unroll
        for (int s2 = 0; s2 < 4; s2++) {               // four k16 slices
            uint32_t af[4][4], bf[2][4];               // bf[p] = {b0,b1 tile2p, b0,b1 tile2p+1}
            #pragma unroll
            for (int i = 0; i < 4; i++)
                LDSM4(af[i], stA + i * (16 * ROWB) + s2 * 32);
            #pragma unroll
            for (int p = 0; p < 2; p++)
                LDSM4(bf[p], stB + p * (16 * ROWB) + s2 * 32);
            #pragma unroll
            for (int i = 0; i < 4; i++)
                #pragma unroll
                for (int p = 0; p < 2; p++) {
                    mma_f16(acc[i][2 * p + 0], af[i], &bf[p][0]);
                    mma_f16(acc[i][2 * p + 1], af[i], &bf[p][2]);
                }
        }
        s = (s == NS - 1) ? 0 : s + 1;
    }

    // epilogue
    #pragma unroll
    for (int i = 0; i < 4; i++) {
        int t0 = m0 + wm * 64 + i * 16 + grp;
        #pragma unroll
        for (int j = 0; j < 4; j++) {
            int n = n0 + wn * 32 + j * 8 + 2 * tig;
            if (PART) {
                float* C = (float*)Cout + (size_t)blockIdx.z * TT * ER;
                float2 v0 = {acc[i][j][0], acc[i][j][1]};
                float2 v1 = {acc[i][j][2], acc[i][j][3]};
                *reinterpret_cast<float2*>(&C[(size_t)t0 * Nsz + n]) = v0;
                *reinterpret_cast<float2*>(&C[(size_t)(t0 + 8) * Nsz + n]) = v1;
            } else if (GELU) {
                __half2* C = (__half2*)Cout;
                float bv0 = bias[n], bv1 = bias[n + 1];
                C[((size_t)t0 * Nsz + n) >> 1] = __floats2half2_rn(
                    gelu_new_f(acc[i][j][0] + bv0), gelu_new_f(acc[i][j][1] + bv1));
                C[((size_t)(t0 + 8) * Nsz + n) >> 1] = __floats2half2_rn(
                    gelu_new_f(acc[i][j][2] + bv0), gelu_new_f(acc[i][j][3] + bv1));
            } else {
                float* C = (float*)Cout;
                float bv0 = bias[n], bv1 = bias[n + 1];
                float2 v0 = {acc[i][j][0] + bv0, acc[i][j][1] + bv1};
                float2 v1 = {acc[i][j][2] + bv0, acc[i][j][3] + bv1};
                *reinterpret_cast<float2*>(&C[(size_t)t0 * Nsz + n]) = v0;
                *reinterpret_cast<float2*>(&C[(size_t)(t0 + 8) * Nsz + n]) = v1;
            }
        }
    }
}

// ---------------- launch --------------------------------------------------------
extern "C" void kernel_launch(void* const* d_in, const int* in_sizes, int n_in,
                              void* d_out, int out_size) {
    const float* x  = (const float*)d_in[0];
    const int*   ei = (const int*)  d_in[1];
    const float* W1 = (const float*)d_in[2];
    const float* b1 = (const float*)d_in[3];
    const float* A1 = (const float*)d_in[4];
    const float* B1 = (const float*)d_in[5];
    const float* W2 = (const float*)d_in[6];
    const float* b2 = (const float*)d_in[7];
    const float* A2 = (const float*)d_in[8];
    const float* B2 = (const float*)d_in[9];
    float* out = (float*)d_out;

    __half *pW1, *pW2, *pB1, *pB2, *pA1, *pA2, *pX, *pY, *pZ1, *pZ2;
    float* pZp;
    cudaGetSymbolAddress((void**)&pW1, g_W1h);
    cudaGetSymbolAddress((void**)&pW2, g_W2h);
    cudaGetSymbolAddress((void**)&pB1, g_B1h);
    cudaGetSymbolAddress((void**)&pB2, g_B2h);
    cudaGetSymbolAddress((void**)&pA1, g_A1h);
    cudaGetSymbolAddress((void**)&pA2, g_A2h);
    cudaGetSymbolAddress((void**)&pX,  g_Xh);
    cudaGetSymbolAddress((void**)&pY,  g_Yh);
    cudaGetSymbolAddress((void**)&pZ1, g_Z1h);
    cudaGetSymbolAddress((void**)&pZ2, g_Z2h);
    cudaGetSymbolAddress((void**)&pZp, g_Zp);

    cudaFuncSetAttribute(moe_gemm_h<DD, true,  true,  false>,
                         cudaFuncAttributeMaxDynamicSharedMemorySize, SMEMSZ);
    cudaFuncSetAttribute(moe_gemm_h<HH, true,  false, false>,
                         cudaFuncAttributeMaxDynamicSharedMemorySize, SMEMSZ);
    cudaFuncSetAttribute(moe_gemm_h<DD, false, false, true>,
                         cudaFuncAttributeMaxDynamicSharedMemorySize, SMEMSZ);
    cudaFuncSetAttribute(moe_gemm_h<HH, false, false, true>,
                         cudaFuncAttributeMaxDynamicSharedMemorySize, SMEMSZ);

    // one merged conversion for all 7 tensors
    ConvSeg s0 = {(const float4*)W1, (__half2*)pW1, HH * DD / 4};
    ConvSeg s1 = {(const float4*)W2, (__half2*)pW2, DD * HH / 4};
    ConvSeg s2 = {(const float4*)x,  (__half2*)pX,  TT * DD / 4};
    ConvSeg s3 = {(const float4*)B1, (__half2*)pB1, NE * HH * RRK / 4};
    ConvSeg s4 = {(const float4*)B2, (__half2*)pB2, NE * DD * RRK / 4};
    ConvSeg s5 = {(const float4*)A1, (__half2*)pA1, ER * DD / 4};
    ConvSeg s6 = {(const float4*)A2, (__half2*)pA2, ER * HH / 4};
    int total4 = s0.n4 + s1.n4 + s2.n4 + s3.n4 + s4.n4 + s5.n4 + s6.n4;
    tohalf_all_k<<<2048, 256>>>(s0, s1, s2, s3, s4, s5, s6, total4);

    // Z1 partials: split-K over K=2048 (4 chunks of 512)
    moe_gemm_h<DD, false, false, true><<<dim3(1, TT / BM, SPLIT1), 256, SMEMSZ>>>(
        pX, nullptr, pA1, nullptr, nullptr, pZp, ER, (DD / SPLIT1) / BK, DD / SPLIT1);
    zreduce_k<SPLIT1><<<TT * ER / 256, 256>>>(pZp, ei, pZ1);

    // fc1: Y = half(gelu(X@W1^T + b1 + Z1@B1^T))
    moe_gemm_h<DD, true, true, false><<<dim3(HH / BN, TT / BM), 256, SMEMSZ>>>(
        pX, pZ1, pW1, pB1, b1, pY, HH, (DD + ER) / BK, 0);

    // Z2 partials: split-K over K=8192 (8 chunks of 1024)
    moe_gemm_h<HH, false, false, true><<<dim3(1, TT / BM, SPLIT2), 256, SMEMSZ>>>(
        pY, nullptr, pA2, nullptr, nullptr, pZp, ER, (HH / SPLIT2) / BK, HH / SPLIT2);
    zreduce_k<SPLIT2><<<TT * ER / 256, 256>>>(pZp, ei, pZ2);

    // fc2: out = Y@W2^T + b2 + Z2@B2^T  (fp32 out)
    moe_gemm_h<HH, true, false, false><<<dim3(DD / BN, TT / BM), 256, SMEMSZ>>>(
        pY, pZ2, pW2, pB2, b2, out, DD, (HH + ER) / BK, 0);
}

// round 13
// speedup vs baseline: 4.0841x; 1.0312x over previous
#include <cuda_runtime.h>
#include <cuda_fp16.h>
#include <cstdint>

#define TT 4096
#define DD 2048
#define HH 8192
#define NE 8
#define RRK 16
#define ER 128
#define SCAL 2.0f

#define BM 128
#define BN 128
#define BK 64                  // 64 halfs of K per tile
#define NS 3
#define RS 36                  // smem row stride in words (144 B) — LDS & ldmatrix conflict-free
#define ROWB 144
#define TILEB (BM * RS * 4)    // 18432 B per operand tile
#define SMEMSZ (NS * 2 * TILEB) // 110592 B -> 2 CTAs/SM
#define NTHR 128               // 4 warps (2x2 of 64x64)

#define SPLIT1 4
#define SPLIT2 8

// ---------------- scratch (device globals) ------------------------------------
__device__ __half g_W1h[(size_t)HH * DD];
__device__ __half g_W2h[(size_t)DD * HH];
__device__ __half g_B1h[(size_t)NE * HH * RRK];
__device__ __half g_B2h[(size_t)NE * DD * RRK];
__device__ __half g_A1h[(size_t)ER * DD];
__device__ __half g_A2h[(size_t)ER * HH];
__device__ __half g_Xh [(size_t)TT * DD];
__device__ __half g_Yh [(size_t)TT * HH];
__device__ __half g_Z1h[TT * ER];
__device__ __half g_Z2h[TT * ER];
__device__ float  g_Zp [(size_t)SPLIT2 * TT * ER];   // split-K partials (fp32)

// ---------------- helpers ------------------------------------------------------
__device__ __forceinline__ void cp16(uint32_t s, const void* g) {
    asm volatile("cp.async.cg.shared.global [%0], [%1], 16;" :: "r"(s), "l"(g));
}
__device__ __forceinline__ float gelu_new_f(float x) {
    float x3 = x * x * x;
    float inner = 0.7978845608028654f * (x + 0.044715f * x3);
    return 0.5f * x * (1.0f + tanhf(inner));
}
__device__ __forceinline__ void mma_f16(float* c, const uint32_t* a, const uint32_t* b) {
    asm volatile(
        "mma.sync.aligned.m16n8k16.row.col.f32.f16.f16.f32 "
        "{%0,%1,%2,%3}, {%4,%5,%6,%7}, {%8,%9}, {%0,%1,%2,%3};"
        : "+f"(c[0]), "+f"(c[1]), "+f"(c[2]), "+f"(c[3])
        : "r"(a[0]), "r"(a[1]), "r"(a[2]), "r"(a[3]), "r"(b[0]), "r"(b[1]));
}
#define LDSM4(d, a) \
    asm volatile("ldmatrix.sync.aligned.m8n8.x4.shared.b16 {%0,%1,%2,%3}, [%4];" \
        : "=r"((d)[0]), "=r"((d)[1]), "=r"((d)[2]), "=r"((d)[3]) : "r"(a))

// ---------------- merged fp32 -> fp16 conversion (all 7 tensors) ---------------
struct ConvSeg { const float4* src; __half2* dst; int n4; };

__global__ void tohalf_all_k(ConvSeg s0, ConvSeg s1, ConvSeg s2, ConvSeg s3,
                             ConvSeg s4, ConvSeg s5, ConvSeg s6, int total4) {
    ConvSeg segs[7] = {s0, s1, s2, s3, s4, s5, s6};
    for (int i = blockIdx.x * blockDim.x + threadIdx.x; i < total4;
         i += gridDim.x * blockDim.x) {
        int r = i;
        #pragma unroll
        for (int k = 0; k < 7; k++) {
            if (r < segs[k].n4) {
                float4 v = segs[k].src[r];
                segs[k].dst[2 * r + 0] = __floats2half2_rn(v.x, v.y);
                segs[k].dst[2 * r + 1] = __floats2half2_rn(v.z, v.w);
                break;
            }
            r -= segs[k].n4;
        }
    }
}

// ---------------- Z reduce: sum split-K partials, mask, scale, -> half ---------
template<int SPLIT>
__global__ void zreduce_k(const float* __restrict__ Zp, const int* __restrict__ eidx,
                          __half* __restrict__ Z) {
    int idx = blockIdx.x * blockDim.x + threadIdx.x;   // t*ER + j
    int t = idx >> 7, j = idx & 127;
    float v = 0.f;
    if ((j >> 4) == eidx[t]) {
        #pragma unroll
        for (int s = 0; s < SPLIT; s++) v += Zp[(size_t)s * TT * ER + idx];
        v *= SCAL;
    }
    Z[idx] = __float2half_rn(v);
}

// ---------------- fp16 GEMM: C[T,N] = [A0|AL] @ [W|BL]^T -----------------------
// 3-stage cp.async ring, one __syncthreads per ktile, BK=64, ldmatrix fragments,
// 4 warps of 64x64 (128 threads).
template<int K0, bool TAIL, bool GELU, bool PART>
__global__ void __launch_bounds__(NTHR, 2)
moe_gemm_h(const __half* __restrict__ A0, const __half* __restrict__ AL,
           const __half* __restrict__ W,  const __half* __restrict__ BL,
           const float* __restrict__ bias, void* __restrict__ Cout,
           int Nsz, int nkt, int kch) {
    extern __shared__ __align__(128) char smem[];
    const int NK = nkt;
    const int kbase = PART ? blockIdx.z * kch : 0;
    const int m0 = blockIdx.y * BM, n0 = blockIdx.x * BN;
    const int tid  = threadIdx.x;
    const int warp = tid >> 5, wm = warp >> 1, wn = warp & 1;   // 2x2 warps, 64x64
    const int lane = tid & 31, grp = lane >> 2, tig = lane & 3;
    const int lr = tid >> 3, lc = tid & 7;                       // loader: 16 rows x 8 chunks

    float acc[4][8][4];
    #pragma unroll
    for (int i = 0; i < 4; i++)
        #pragma unroll
        for (int j = 0; j < 8; j++)
            #pragma unroll
            for (int c = 0; c < 4; c++) acc[i][j][c] = 0.f;

    const uint32_t sA = (uint32_t)__cvta_generic_to_shared(smem);
    const uint32_t sB = sA + NS * TILEB;

    // ldmatrix per-lane base addresses (stage 0)
    const int l7 = lane & 7, lb = (lane >> 3) & 1, lh = lane >> 4;
    // A: matrices [m..m+7 | m+8..m+15] x [k | k+8]
    const uint32_t lmA = sA + (uint32_t)((wm * 64 + l7 + lb * 8) * ROWB + lh * 16);
    // B: matrices [n..n+7 k | n..n+7 k+8 | n+8..n+15 k | n+8..n+15 k+8]
    const uint32_t lmB = sB + (uint32_t)((wn * 64 + l7 + lh * 8) * ROWB + lb * 16);

    auto load_tiles = [&](int kt, int buf) {
        int kk = kbase + kt * BK + lc * 8;
        #pragma unroll
        for (int p = 0; p < 8; p++) {
            int row = lr + p * 16;
            const __half* gp = (!TAIL || kk < K0)
                ? A0 + (size_t)(m0 + row) * K0 + kk
                : AL + (size_t)(m0 + row) * ER + (kk - K0);
            cp16(sA + (uint32_t)(buf * TILEB + row * ROWB + lc * 16), gp);
            const __half* gq;
            if (!TAIL || kk < K0) {
                gq = W + (size_t)(n0 + row) * K0 + kk;
            } else {
                int j = kk - K0;                   // e = j>>4, r = j&15
                gq = BL + ((size_t)(j >> 4) * Nsz + (n0 + row)) * RRK + (j & 15);
            }
            cp16(sB + (uint32_t)(buf * TILEB + row * ROWB + lc * 16), gq);
        }
    };

    load_tiles(0, 0);
    asm volatile("cp.async.commit_group;");
    load_tiles(1, 1);
    asm volatile("cp.async.commit_group;");

    int s = 0;
    for (int kt = 0; kt < NK; ++kt) {
        asm volatile("cp.async.wait_group 1;");
        __syncthreads();

        if (kt + 2 < NK) load_tiles(kt + 2, (kt + 2) % NS);
        asm volatile("cp.async.commit_group;");

        const uint32_t stA = lmA + s * TILEB;
        const uint32_t stB = lmB + s * TILEB;
        #pragma unroll
        for (int s2 = 0; s2 < 4; s2++) {               // four k16 slices
            uint32_t af[4][4], bf[4][4];               // bf[p] = {b0,b1 tile2p, b0,b1 tile2p+1}
            #pragma unroll
            for (int i = 0; i < 4; i++)
                LDSM4(af[i], stA + i * (16 * ROWB) + s2 * 32);
            #pragma unroll
            for (int p = 0; p < 4; p++)
                LDSM4(bf[p], stB + p * (16 * ROWB) + s2 * 32);
            #pragma unroll
            for (int i = 0; i < 4; i++)
                #pragma unroll
                for (int p = 0; p < 4; p++) {
                    mma_f16(acc[i][2 * p + 0], af[i], &bf[p][0]);
                    mma_f16(acc[i][2 * p + 1], af[i], &bf[p][2]);
                }
        }
        s = (s == NS - 1) ? 0 : s + 1;
    }

    // epilogue
    #pragma unroll
    for (int i = 0; i < 4; i++) {
        int t0 = m0 + wm * 64 + i * 16 + grp;
        #pragma unroll
        for (int j = 0; j < 8; j++) {
            int n = n0 + wn * 64 + j * 8 + 2 * tig;
            if (PART) {
                float* C = (float*)Cout + (size_t)blockIdx.z * TT * ER;
                float2 v0 = {acc[i][j][0], acc[i][j][1]};
                float2 v1 = {acc[i][j][2], acc[i][j][3]};
                *reinterpret_cast<float2*>(&C[(size_t)t0 * Nsz + n]) = v0;
                *reinterpret_cast<float2*>(&C[(size_t)(t0 + 8) * Nsz + n]) = v1;
            } else if (GELU) {
                __half2* C = (__half2*)Cout;
                float bv0 = bias[n], bv1 = bias[n + 1];
                C[((size_t)t0 * Nsz + n) >> 1] = __floats2half2_rn(
                    gelu_new_f(acc[i][j][0] + bv0), gelu_new_f(acc[i][j][1] + bv1));
                C[((size_t)(t0 + 8) * Nsz + n) >> 1] = __floats2half2_rn(
                    gelu_new_f(acc[i][j][2] + bv0), gelu_new_f(acc[i][j][3] + bv1));
            } else {
                float* C = (float*)Cout;
                float bv0 = bias[n], bv1 = bias[n + 1];
                float2 v0 = {acc[i][j][0] + bv0, acc[i][j][1] + bv1};
                float2 v1 = {acc[i][j][2] + bv0, acc[i][j][3] + bv1};
                *reinterpret_cast<float2*>(&C[(size_t)t0 * Nsz + n]) = v0;
                *reinterpret_cast<float2*>(&C[(size_t)(t0 + 8) * Nsz + n]) = v1;
            }
        }
    }
}

// ---------------- launch --------------------------------------------------------
extern "C" void kernel_launch(void* const* d_in, const int* in_sizes, int n_in,
                              void* d_out, int out_size) {
    const float* x  = (const float*)d_in[0];
    const int*   ei = (const int*)  d_in[1];
    const float* W1 = (const float*)d_in[2];
    const float* b1 = (const float*)d_in[3];
    const float* A1 = (const float*)d_in[4];
    const float* B1 = (const float*)d_in[5];
    const float* W2 = (const float*)d_in[6];
    const float* b2 = (const float*)d_in[7];
    const float* A2 = (const float*)d_in[8];
    const float* B2 = (const float*)d_in[9];
    float* out = (float*)d_out;

    __half *pW1, *pW2, *pB1, *pB2, *pA1, *pA2, *pX, *pY, *pZ1, *pZ2;
    float* pZp;
    cudaGetSymbolAddress((void**)&pW1, g_W1h);
    cudaGetSymbolAddress((void**)&pW2, g_W2h);
    cudaGetSymbolAddress((void**)&pB1, g_B1h);
    cudaGetSymbolAddress((void**)&pB2, g_B2h);
    cudaGetSymbolAddress((void**)&pA1, g_A1h);
    cudaGetSymbolAddress((void**)&pA2, g_A2h);
    cudaGetSymbolAddress((void**)&pX,  g_Xh);
    cudaGetSymbolAddress((void**)&pY,  g_Yh);
    cudaGetSymbolAddress((void**)&pZ1, g_Z1h);
    cudaGetSymbolAddress((void**)&pZ2, g_Z2h);
    cudaGetSymbolAddress((void**)&pZp, g_Zp);

    cudaFuncSetAttribute(moe_gemm_h<DD, true,  true,  false>,
                         cudaFuncAttributeMaxDynamicSharedMemorySize, SMEMSZ);
    cudaFuncSetAttribute(moe_gemm_h<HH, true,  false, false>,
                         cudaFuncAttributeMaxDynamicSharedMemorySize, SMEMSZ);
    cudaFuncSetAttribute(moe_gemm_h<DD, false, false, true>,
                         cudaFuncAttributeMaxDynamicSharedMemorySize, SMEMSZ);
    cudaFuncSetAttribute(moe_gemm_h<HH, false, false, true>,
                         cudaFuncAttributeMaxDynamicSharedMemorySize, SMEMSZ);

    // one merged conversion for all 7 tensors
    ConvSeg s0 = {(const float4*)W1, (__half2*)pW1, HH * DD / 4};
    ConvSeg s1 = {(const float4*)W2, (__half2*)pW2, DD * HH / 4};
    ConvSeg s2 = {(const float4*)x,  (__half2*)pX,  TT * DD / 4};
    ConvSeg s3 = {(const float4*)B1, (__half2*)pB1, NE * HH * RRK / 4};
    ConvSeg s4 = {(const float4*)B2, (__half2*)pB2, NE * DD * RRK / 4};
    ConvSeg s5 = {(const float4*)A1, (__half2*)pA1, ER * DD / 4};
    ConvSeg s6 = {(const float4*)A2, (__half2*)pA2, ER * HH / 4};
    int total4 = s0.n4 + s1.n4 + s2.n4 + s3.n4 + s4.n4 + s5.n4 + s6.n4;
    tohalf_all_k<<<2048, 256>>>(s0, s1, s2, s3, s4, s5, s6, total4);

    // Z1 partials: split-K over K=2048 (4 chunks of 512)
    moe_gemm_h<DD, false, false, true><<<dim3(1, TT / BM, SPLIT1), NTHR, SMEMSZ>>>(
        pX, nullptr, pA1, nullptr, nullptr, pZp, ER, (DD / SPLIT1) / BK, DD / SPLIT1);
    zreduce_k<SPLIT1><<<TT * ER / 256, 256>>>(pZp, ei, pZ1);

    // fc1: Y = half(gelu(X@W1^T + b1 + Z1@B1^T))
    moe_gemm_h<DD, true, true, false><<<dim3(HH / BN, TT / BM), NTHR, SMEMSZ>>>(
        pX, pZ1, pW1, pB1, b1, pY, HH, (DD + ER) / BK, 0);

    // Z2 partials: split-K over K=8192 (8 chunks of 1024)
    moe_gemm_h<HH, false, false, true><<<dim3(1, TT / BM, SPLIT2), NTHR, SMEMSZ>>>(
        pY, nullptr, pA2, nullptr, nullptr, pZp, ER, (HH / SPLIT2) / BK, HH / SPLIT2);
    zreduce_k<SPLIT2><<<TT * ER / 256, 256>>>(pZp, ei, pZ2);

    // fc2: out = Y@W2^T + b2 + Z2@B2^T  (fp32 out)
    moe_gemm_h<HH, true, false, false><<<dim3(DD / BN, TT / BM), NTHR, SMEMSZ>>>(
        pY, pZ2, pW2, pB2, b2, out, DD, (HH + ER) / BK, 0);
}